// round 2
// baseline (speedup 1.0000x reference)
#include <cuda_runtime.h>
#include <math.h>

// Problem constants
#define B_  2
#define L_  1024
#define S_  4096
#define H_  16
#define HD  64
#define LD  1024   // latent dim
#define ID  2048   // input dim
#define R_  256    // latent rank

// Scratch (device globals: allocation-free)
__device__ float g_Q[B_ * L_ * LD];      // 8 MB
__device__ float g_comp[B_ * S_ * R_];   // 8 MB
__device__ float g_K[B_ * S_ * LD];      // 32 MB
__device__ float g_V[B_ * S_ * LD];      // 32 MB
__device__ float g_AO[B_ * L_ * LD];     // 8 MB

// ---------------------------------------------------------------------------
// Generic tiled GEMM: C[M,N] = A[M,K] @ B[K,N] + bias[N]
// Requirements: M%64==0, N%64==0, K%16==0 (all call sites satisfy this).
// Block = 256 threads (16x16), each thread computes a 4x4 tile of a 64x64 block.
// ---------------------------------------------------------------------------
__global__ __launch_bounds__(256) void gemm_bias(
    const float* __restrict__ A, const float* __restrict__ Bm,
    const float* __restrict__ bias, float* __restrict__ C,
    int K, int lda, int ldb, int ldc)
{
    __shared__ float As[16][68];  // [k][m], padded for float4 + fewer conflicts
    __shared__ float Bs[16][64];  // [k][n]

    const int tx = threadIdx.x, ty = threadIdx.y;
    const int tid = ty * 16 + tx;
    const int m0 = blockIdx.y * 64, n0 = blockIdx.x * 64;

    const float* Ab = A + (size_t)m0 * lda;
    const float* Bb = Bm + n0;

    float acc[4][4] = {};

    const int kk = tid & 15;       // A-load: k within tile
    const int mb = tid >> 4;       // A-load: m base (0..15)
    const int nn = tid & 63;       // B-load: n within tile
    const int kb = tid >> 6;       // B-load: k base (0..3)

    for (int k0 = 0; k0 < K; k0 += 16) {
#pragma unroll
        for (int r = 0; r < 4; r++) {
            int m = mb + r * 16;
            As[kk][m] = Ab[(size_t)m * lda + k0 + kk];
        }
#pragma unroll
        for (int r = 0; r < 4; r++) {
            int k = kb + r * 4;
            Bs[k][nn] = Bb[(size_t)(k0 + k) * ldb + nn];
        }
        __syncthreads();
#pragma unroll
        for (int k = 0; k < 16; k++) {
            float4 av = *(const float4*)&As[k][ty * 4];
            float4 bv = *(const float4*)&Bs[k][tx * 4];
            float a[4] = {av.x, av.y, av.z, av.w};
            float b[4] = {bv.x, bv.y, bv.z, bv.w};
#pragma unroll
            for (int i = 0; i < 4; i++)
#pragma unroll
                for (int j = 0; j < 4; j++)
                    acc[i][j] = fmaf(a[i], b[j], acc[i][j]);
        }
        __syncthreads();
    }

    float bvv[4] = {0.f, 0.f, 0.f, 0.f};
    if (bias) {
#pragma unroll
        for (int j = 0; j < 4; j++) bvv[j] = bias[n0 + tx * 4 + j];
    }
#pragma unroll
    for (int i = 0; i < 4; i++) {
        int m = m0 + ty * 4 + i;
        float4 o;
        o.x = acc[i][0] + bvv[0];
        o.y = acc[i][1] + bvv[1];
        o.z = acc[i][2] + bvv[2];
        o.w = acc[i][3] + bvv[3];
        *(float4*)&C[(size_t)m * ldc + n0 + tx * 4] = o;
    }
}

// ---------------------------------------------------------------------------
// Scores: per (b,h), S_tile x L_tile of Q @ K^T * (1/sqrt(64)).
// D=64 is fully resident in smem -> single K-pass.
// attn layout: [b,h,l,s] row-major (matches reference attn_weights).
// ---------------------------------------------------------------------------
__global__ __launch_bounds__(256) void scores_kernel(
    const float* __restrict__ Q, const float* __restrict__ Kb,
    float* __restrict__ attn)
{
    __shared__ float Qs[64][68];  // [d][l]
    __shared__ float Ks[64][68];  // [d][s]

    const int z = blockIdx.z;            // b*16 + h
    const int b = z >> 4, h = z & 15;
    const int l0 = blockIdx.y * 64, s0 = blockIdx.x * 64;
    const int tx = threadIdx.x, ty = threadIdx.y;
    const int tid = ty * 16 + tx;

    const float* Qb  = Q  + ((size_t)(b * L_ + l0)) * LD + h * HD;
    const float* Kbb = Kb + ((size_t)(b * S_ + s0)) * LD + h * HD;

    {
        const int d = tid & 63;
        const int rb = tid >> 6;  // 0..3
#pragma unroll
        for (int r = 0; r < 16; r++) {
            int row = rb + r * 4;
            Qs[d][row] = Qb[(size_t)row * LD + d];
            Ks[d][row] = Kbb[(size_t)row * LD + d];
        }
    }
    __syncthreads();

    float acc[4][4] = {};
#pragma unroll 4
    for (int d = 0; d < 64; d++) {
        float4 qv = *(const float4*)&Qs[d][ty * 4];
        float4 kv = *(const float4*)&Ks[d][tx * 4];
        float q[4] = {qv.x, qv.y, qv.z, qv.w};
        float k[4] = {kv.x, kv.y, kv.z, kv.w};
#pragma unroll
        for (int i = 0; i < 4; i++)
#pragma unroll
            for (int j = 0; j < 4; j++)
                acc[i][j] = fmaf(q[i], k[j], acc[i][j]);
    }

    const float scale = 0.125f;  // 1/sqrt(64)
#pragma unroll
    for (int i = 0; i < 4; i++) {
        size_t row = (size_t)z * L_ + l0 + ty * 4 + i;
        float4 o;
        o.x = acc[i][0] * scale;
        o.y = acc[i][1] * scale;
        o.z = acc[i][2] * scale;
        o.w = acc[i][3] * scale;
        *(float4*)&attn[row * S_ + s0 + tx * 4] = o;
    }
}

// ---------------------------------------------------------------------------
// Row softmax over S=4096, in place. One block (256 thr) per row; 16 elems/thr.
// ---------------------------------------------------------------------------
__global__ __launch_bounds__(256) void softmax_kernel(float* __restrict__ attn)
{
    __shared__ float red[256];
    const size_t row = blockIdx.x;
    float4* p4 = (float4*)(attn + row * (size_t)S_);
    const int t = threadIdx.x;

    float v[16];
    float mx = -INFINITY;
#pragma unroll
    for (int q = 0; q < 4; q++) {
        float4 x = p4[t + 256 * q];
        v[q * 4 + 0] = x.x; v[q * 4 + 1] = x.y;
        v[q * 4 + 2] = x.z; v[q * 4 + 3] = x.w;
        mx = fmaxf(mx, fmaxf(fmaxf(x.x, x.y), fmaxf(x.z, x.w)));
    }
    red[t] = mx;
    __syncthreads();
    for (int s = 128; s > 0; s >>= 1) {
        if (t < s) red[t] = fmaxf(red[t], red[t + s]);
        __syncthreads();
    }
    mx = red[0];
    __syncthreads();

    float sum = 0.f;
#pragma unroll
    for (int i = 0; i < 16; i++) {
        v[i] = __expf(v[i] - mx);
        sum += v[i];
    }
    red[t] = sum;
    __syncthreads();
    for (int s = 128; s > 0; s >>= 1) {
        if (t < s) red[t] += red[t + s];
        __syncthreads();
    }
    const float inv = 1.0f / red[0];

#pragma unroll
    for (int q = 0; q < 4; q++) {
        float4 o;
        o.x = v[q * 4 + 0] * inv; o.y = v[q * 4 + 1] * inv;
        o.z = v[q * 4 + 2] * inv; o.w = v[q * 4 + 3] * inv;
        p4[t + 256 * q] = o;
    }
}

// ---------------------------------------------------------------------------
// attn_out[b,l,h*64+d] = sum_s attn[b,h,l,s] * V[b,s,h*64+d]
// Per z=(b,h): (1024 x 4096) @ (4096 x 64). Block covers 64 rows x full 64 cols.
// ---------------------------------------------------------------------------
__global__ __launch_bounds__(256) void attnv_kernel(
    const float* __restrict__ attn, const float* __restrict__ V,
    float* __restrict__ AO)
{
    __shared__ float Ps[16][68];  // [k][m]
    __shared__ float Vs[16][64];  // [k][n]

    const int z = blockIdx.z, b = z >> 4, h = z & 15;
    const int m0 = blockIdx.y * 64;
    const int tx = threadIdx.x, ty = threadIdx.y;
    const int tid = ty * 16 + tx;

    const float* Pb = attn + ((size_t)z * L_ + m0) * S_;
    const float* Vb = V + ((size_t)b * S_) * LD + h * HD;

    float acc[4][4] = {};

    const int kk = tid & 15;
    const int mb = tid >> 4;
    const int nn = tid & 63;
    const int kb = tid >> 6;

    for (int k0 = 0; k0 < S_; k0 += 16) {
#pragma unroll
        for (int r = 0; r < 4; r++) {
            int m = mb + r * 16;
            Ps[kk][m] = Pb[(size_t)m * S_ + k0 + kk];
        }
#pragma unroll
        for (int r = 0; r < 4; r++) {
            int k = kb + r * 4;
            Vs[k][nn] = Vb[(size_t)(k0 + k) * LD + nn];
        }
        __syncthreads();
#pragma unroll
        for (int k = 0; k < 16; k++) {
            float4 av = *(const float4*)&Ps[k][ty * 4];
            float4 bv = *(const float4*)&Vs[k][tx * 4];
            float a[4] = {av.x, av.y, av.z, av.w};
            float bb[4] = {bv.x, bv.y, bv.z, bv.w};
#pragma unroll
            for (int i = 0; i < 4; i++)
#pragma unroll
                for (int j = 0; j < 4; j++)
                    acc[i][j] = fmaf(a[i], bb[j], acc[i][j]);
        }
        __syncthreads();
    }

    float* Cb = AO + ((size_t)(b * L_ + m0)) * LD + h * HD;
#pragma unroll
    for (int i = 0; i < 4; i++) {
        float4 o;
        o.x = acc[i][0]; o.y = acc[i][1]; o.z = acc[i][2]; o.w = acc[i][3];
        *(float4*)&Cb[(size_t)(ty * 4 + i) * LD + tx * 4] = o;
    }
}

// ---------------------------------------------------------------------------
// Launch
// ---------------------------------------------------------------------------
extern "C" void kernel_launch(void* const* d_in, const int* in_sizes, int n_in,
                              void* d_out, int out_size)
{
    const float* latent = (const float*)d_in[0];
    const float* x      = (const float*)d_in[1];
    const float* Wq = (const float*)d_in[2];  const float* bq = (const float*)d_in[3];
    const float* Wc = (const float*)d_in[4];  const float* bc = (const float*)d_in[5];
    const float* Wk = (const float*)d_in[6];  const float* bk = (const float*)d_in[7];
    const float* Wv = (const float*)d_in[8];  const float* bv = (const float*)d_in[9];
    const float* Wo = (const float*)d_in[10]; const float* bo = (const float*)d_in[11];

    float* out  = (float*)d_out;                       // (B, L, 1024)
    float* attn = out + (size_t)B_ * L_ * LD;          // (B, H, L, S)

    float *Qp, *Cp, *Kp, *Vp, *AOp;
    cudaGetSymbolAddress((void**)&Qp,  g_Q);
    cudaGetSymbolAddress((void**)&Cp,  g_comp);
    cudaGetSymbolAddress((void**)&Kp,  g_K);
    cudaGetSymbolAddress((void**)&Vp,  g_V);
    cudaGetSymbolAddress((void**)&AOp, g_AO);

    dim3 blk(16, 16);

    // Q = latent @ Wq + bq : (2048 x 1024) x (1024 x 1024)
    gemm_bias<<<dim3(LD / 64, (B_ * L_) / 64), blk>>>(latent, Wq, bq, Qp, LD, LD, LD, LD);
    // compressed = x @ Wc + bc : (8192 x 2048) x (2048 x 256)
    gemm_bias<<<dim3(R_ / 64, (B_ * S_) / 64), blk>>>(x, Wc, bc, Cp, ID, ID, R_, R_);
    // K = compressed @ Wk + bk : (8192 x 256) x (256 x 1024)
    gemm_bias<<<dim3(LD / 64, (B_ * S_) / 64), blk>>>(Cp, Wk, bk, Kp, R_, R_, LD, LD);
    // V = compressed @ Wv + bv
    gemm_bias<<<dim3(LD / 64, (B_ * S_) / 64), blk>>>(Cp, Wv, bv, Vp, R_, R_, LD, LD);
    // scores -> attn region of d_out (raw, scaled)
    scores_kernel<<<dim3(S_ / 64, L_ / 64, B_ * H_), blk>>>(Qp, Kp, attn);
    // softmax in place
    softmax_kernel<<<B_ * H_ * L_, 256>>>(attn);
    // attn @ V -> attn_out
    attnv_kernel<<<dim3(1, L_ / 64, B_ * H_), blk>>>(attn, Vp, AOp);
    // output = attn_out @ Wo + bo
    gemm_bias<<<dim3(LD / 64, (B_ * L_) / 64), blk>>>(AOp, Wo, bo, out, LD, LD, LD, LD);
}

// round 3
// speedup vs baseline: 1.0020x; 1.0020x over previous
#include <cuda_runtime.h>
#include <math.h>

// Problem constants
#define B_  2
#define L_  1024
#define S_  4096
#define H_  16
#define HD  64
#define LD  1024   // latent dim
#define ID  2048   // input dim
#define R_  256    // latent rank

// Scratch (device globals: allocation-free)
__device__ float g_Q[B_ * L_ * LD];      // 8 MB
__device__ float g_comp[B_ * S_ * R_];   // 8 MB
__device__ float g_K[B_ * S_ * LD];      // 32 MB
__device__ float g_V[B_ * S_ * LD];      // 32 MB
__device__ float g_AO[B_ * L_ * LD];     // 8 MB

// ---------------------------------------------------------------------------
// Generic tiled GEMM: C[M,N] = A[M,K] @ B[K,N] + bias[N]
// Requirements: M%64==0, N%64==0, K%16==0 (all call sites satisfy this).
// Block = 256 threads (16x16), each thread computes a 4x4 tile of a 64x64 block.
// ---------------------------------------------------------------------------
__global__ __launch_bounds__(256) void gemm_bias(
    const float* __restrict__ A, const float* __restrict__ Bm,
    const float* __restrict__ bias, float* __restrict__ C,
    int K, int lda, int ldb, int ldc)
{
    __shared__ float As[16][68];  // [k][m], padded for float4 + fewer conflicts
    __shared__ float Bs[16][64];  // [k][n]

    const int tx = threadIdx.x, ty = threadIdx.y;
    const int tid = ty * 16 + tx;
    const int m0 = blockIdx.y * 64, n0 = blockIdx.x * 64;

    const float* Ab = A + (size_t)m0 * lda;
    const float* Bb = Bm + n0;

    float acc[4][4] = {};

    const int kk = tid & 15;       // A-load: k within tile
    const int mb = tid >> 4;       // A-load: m base (0..15)
    const int nn = tid & 63;       // B-load: n within tile
    const int kb = tid >> 6;       // B-load: k base (0..3)

    for (int k0 = 0; k0 < K; k0 += 16) {
#pragma unroll
        for (int r = 0; r < 4; r++) {
            int m = mb + r * 16;
            As[kk][m] = Ab[(size_t)m * lda + k0 + kk];
        }
#pragma unroll
        for (int r = 0; r < 4; r++) {
            int k = kb + r * 4;
            Bs[k][nn] = Bb[(size_t)(k0 + k) * ldb + nn];
        }
        __syncthreads();
#pragma unroll
        for (int k = 0; k < 16; k++) {
            float4 av = *(const float4*)&As[k][ty * 4];
            float4 bv = *(const float4*)&Bs[k][tx * 4];
            float a[4] = {av.x, av.y, av.z, av.w};
            float b[4] = {bv.x, bv.y, bv.z, bv.w};
#pragma unroll
            for (int i = 0; i < 4; i++)
#pragma unroll
                for (int j = 0; j < 4; j++)
                    acc[i][j] = fmaf(a[i], b[j], acc[i][j]);
        }
        __syncthreads();
    }

    float bvv[4] = {0.f, 0.f, 0.f, 0.f};
    if (bias) {
#pragma unroll
        for (int j = 0; j < 4; j++) bvv[j] = bias[n0 + tx * 4 + j];
    }
#pragma unroll
    for (int i = 0; i < 4; i++) {
        int m = m0 + ty * 4 + i;
        float4 o;
        o.x = acc[i][0] + bvv[0];
        o.y = acc[i][1] + bvv[1];
        o.z = acc[i][2] + bvv[2];
        o.w = acc[i][3] + bvv[3];
        *(float4*)&C[(size_t)m * ldc + n0 + tx * 4] = o;
    }
}

// ---------------------------------------------------------------------------
// Scores: per (b,h), S_tile x L_tile of Q @ K^T * (1/sqrt(64)).
// D=64 is fully resident in smem -> single K-pass.
// attn layout: [b,h,l,s] row-major (matches reference attn_weights).
// ---------------------------------------------------------------------------
__global__ __launch_bounds__(256) void scores_kernel(
    const float* __restrict__ Q, const float* __restrict__ Kb,
    float* __restrict__ attn)
{
    __shared__ float Qs[64][68];  // [d][l]
    __shared__ float Ks[64][68];  // [d][s]

    const int z = blockIdx.z;            // b*16 + h
    const int b = z >> 4, h = z & 15;
    const int l0 = blockIdx.y * 64, s0 = blockIdx.x * 64;
    const int tx = threadIdx.x, ty = threadIdx.y;
    const int tid = ty * 16 + tx;

    const float* Qb  = Q  + ((size_t)(b * L_ + l0)) * LD + h * HD;
    const float* Kbb = Kb + ((size_t)(b * S_ + s0)) * LD + h * HD;

    {
        const int d = tid & 63;
        const int rb = tid >> 6;  // 0..3
#pragma unroll
        for (int r = 0; r < 16; r++) {
            int row = rb + r * 4;
            Qs[d][row] = Qb[(size_t)row * LD + d];
            Ks[d][row] = Kbb[(size_t)row * LD + d];
        }
    }
    __syncthreads();

    float acc[4][4] = {};
#pragma unroll 4
    for (int d = 0; d < 64; d++) {
        float4 qv = *(const float4*)&Qs[d][ty * 4];
        float4 kv = *(const float4*)&Ks[d][tx * 4];
        float q[4] = {qv.x, qv.y, qv.z, qv.w};
        float k[4] = {kv.x, kv.y, kv.z, kv.w};
#pragma unroll
        for (int i = 0; i < 4; i++)
#pragma unroll
            for (int j = 0; j < 4; j++)
                acc[i][j] = fmaf(q[i], k[j], acc[i][j]);
    }

    const float scale = 0.125f;  // 1/sqrt(64)
#pragma unroll
    for (int i = 0; i < 4; i++) {
        size_t row = (size_t)z * L_ + l0 + ty * 4 + i;
        float4 o;
        o.x = acc[i][0] * scale;
        o.y = acc[i][1] * scale;
        o.z = acc[i][2] * scale;
        o.w = acc[i][3] * scale;
        *(float4*)&attn[row * S_ + s0 + tx * 4] = o;
    }
}

// ---------------------------------------------------------------------------
// Row softmax over S=4096, in place. One block (256 thr) per row; 16 elems/thr.
// ---------------------------------------------------------------------------
__global__ __launch_bounds__(256) void softmax_kernel(float* __restrict__ attn)
{
    __shared__ float red[256];
    const size_t row = blockIdx.x;
    float4* p4 = (float4*)(attn + row * (size_t)S_);
    const int t = threadIdx.x;

    float v[16];
    float mx = -INFINITY;
#pragma unroll
    for (int q = 0; q < 4; q++) {
        float4 x = p4[t + 256 * q];
        v[q * 4 + 0] = x.x; v[q * 4 + 1] = x.y;
        v[q * 4 + 2] = x.z; v[q * 4 + 3] = x.w;
        mx = fmaxf(mx, fmaxf(fmaxf(x.x, x.y), fmaxf(x.z, x.w)));
    }
    red[t] = mx;
    __syncthreads();
    for (int s = 128; s > 0; s >>= 1) {
        if (t < s) red[t] = fmaxf(red[t], red[t + s]);
        __syncthreads();
    }
    mx = red[0];
    __syncthreads();

    float sum = 0.f;
#pragma unroll
    for (int i = 0; i < 16; i++) {
        v[i] = __expf(v[i] - mx);
        sum += v[i];
    }
    red[t] = sum;
    __syncthreads();
    for (int s = 128; s > 0; s >>= 1) {
        if (t < s) red[t] += red[t + s];
        __syncthreads();
    }
    const float inv = 1.0f / red[0];

#pragma unroll
    for (int q = 0; q < 4; q++) {
        float4 o;
        o.x = v[q * 4 + 0] * inv; o.y = v[q * 4 + 1] * inv;
        o.z = v[q * 4 + 2] * inv; o.w = v[q * 4 + 3] * inv;
        p4[t + 256 * q] = o;
    }
}

// ---------------------------------------------------------------------------
// attn_out[b,l,h*64+d] = sum_s attn[b,h,l,s] * V[b,s,h*64+d]
// Per z=(b,h): (1024 x 4096) @ (4096 x 64). Block covers 64 rows x full 64 cols.
// ---------------------------------------------------------------------------
__global__ __launch_bounds__(256) void attnv_kernel(
    const float* __restrict__ attn, const float* __restrict__ V,
    float* __restrict__ AO)
{
    __shared__ float Ps[16][68];  // [k][m]
    __shared__ float Vs[16][64];  // [k][n]

    const int z = blockIdx.z, b = z >> 4, h = z & 15;
    const int m0 = blockIdx.y * 64;
    const int tx = threadIdx.x, ty = threadIdx.y;
    const int tid = ty * 16 + tx;

    const float* Pb = attn + ((size_t)z * L_ + m0) * S_;
    const float* Vb = V + ((size_t)b * S_) * LD + h * HD;

    float acc[4][4] = {};

    const int kk = tid & 15;
    const int mb = tid >> 4;
    const int nn = tid & 63;
    const int kb = tid >> 6;

    for (int k0 = 0; k0 < S_; k0 += 16) {
#pragma unroll
        for (int r = 0; r < 4; r++) {
            int m = mb + r * 16;
            Ps[kk][m] = Pb[(size_t)m * S_ + k0 + kk];
        }
#pragma unroll
        for (int r = 0; r < 4; r++) {
            int k = kb + r * 4;
            Vs[k][nn] = Vb[(size_t)(k0 + k) * LD + nn];
        }
        __syncthreads();
#pragma unroll
        for (int k = 0; k < 16; k++) {
            float4 av = *(const float4*)&Ps[k][ty * 4];
            float4 bv = *(const float4*)&Vs[k][tx * 4];
            float a[4] = {av.x, av.y, av.z, av.w};
            float bb[4] = {bv.x, bv.y, bv.z, bv.w};
#pragma unroll
            for (int i = 0; i < 4; i++)
#pragma unroll
                for (int j = 0; j < 4; j++)
                    acc[i][j] = fmaf(a[i], bb[j], acc[i][j]);
        }
        __syncthreads();
    }

    float* Cb = AO + ((size_t)(b * L_ + m0)) * LD + h * HD;
#pragma unroll
    for (int i = 0; i < 4; i++) {
        float4 o;
        o.x = acc[i][0]; o.y = acc[i][1]; o.z = acc[i][2]; o.w = acc[i][3];
        *(float4*)&Cb[(size_t)(ty * 4 + i) * LD + tx * 4] = o;
    }
}

// ---------------------------------------------------------------------------
// Launch
// ---------------------------------------------------------------------------
extern "C" void kernel_launch(void* const* d_in, const int* in_sizes, int n_in,
                              void* d_out, int out_size)
{
    const float* latent = (const float*)d_in[0];
    const float* x      = (const float*)d_in[1];
    const float* Wq = (const float*)d_in[2];  const float* bq = (const float*)d_in[3];
    const float* Wc = (const float*)d_in[4];  const float* bc = (const float*)d_in[5];
    const float* Wk = (const float*)d_in[6];  const float* bk = (const float*)d_in[7];
    const float* Wv = (const float*)d_in[8];  const float* bv = (const float*)d_in[9];
    const float* Wo = (const float*)d_in[10]; const float* bo = (const float*)d_in[11];

    float* out  = (float*)d_out;                       // (B, L, 1024)
    float* attn = out + (size_t)B_ * L_ * LD;          // (B, H, L, S)

    float *Qp, *Cp, *Kp, *Vp, *AOp;
    cudaGetSymbolAddress((void**)&Qp,  g_Q);
    cudaGetSymbolAddress((void**)&Cp,  g_comp);
    cudaGetSymbolAddress((void**)&Kp,  g_K);
    cudaGetSymbolAddress((void**)&Vp,  g_V);
    cudaGetSymbolAddress((void**)&AOp, g_AO);

    dim3 blk(16, 16);

    // Q = latent @ Wq + bq : (2048 x 1024) x (1024 x 1024)
    gemm_bias<<<dim3(LD / 64, (B_ * L_) / 64), blk>>>(latent, Wq, bq, Qp, LD, LD, LD, LD);
    // compressed = x @ Wc + bc : (8192 x 2048) x (2048 x 256)
    gemm_bias<<<dim3(R_ / 64, (B_ * S_) / 64), blk>>>(x, Wc, bc, Cp, ID, ID, R_, R_);
    // K = compressed @ Wk + bk : (8192 x 256) x (256 x 1024)
    gemm_bias<<<dim3(LD / 64, (B_ * S_) / 64), blk>>>(Cp, Wk, bk, Kp, R_, R_, LD, LD);
    // V = compressed @ Wv + bv
    gemm_bias<<<dim3(LD / 64, (B_ * S_) / 64), blk>>>(Cp, Wv, bv, Vp, R_, R_, LD, LD);
    // scores -> attn region of d_out (raw, scaled)
    scores_kernel<<<dim3(S_ / 64, L_ / 64, B_ * H_), blk>>>(Qp, Kp, attn);
    // softmax in place
    softmax_kernel<<<B_ * H_ * L_, 256>>>(attn);
    // attn @ V -> attn_out
    attnv_kernel<<<dim3(1, L_ / 64, B_ * H_), blk>>>(attn, Vp, AOp);
    // output = attn_out @ Wo + bo
    gemm_bias<<<dim3(LD / 64, (B_ * L_) / 64), blk>>>(AOp, Wo, bo, out, LD, LD, LD, LD);
}

// round 6
// speedup vs baseline: 1.9518x; 1.9479x over previous
#include <cuda_runtime.h>
#include <cuda_bf16.h>
#include <cstdint>
#include <string.h>
#include <math.h>

#define B_  2
#define L_  1024
#define S_  4096
#define H_  16
#define LD  1024
#define ID  2048
#define R_  256

typedef __nv_bfloat16 bf;

// ---- scratch (device globals, allocation-free) ----
__device__ bf g_Lh[B_*L_*LD],  g_Ll[B_*L_*LD];
__device__ bf g_Xh[B_*S_*ID],  g_Xl[B_*S_*ID];
__device__ bf g_WqT[2][LD*LD], g_WcT[2][R_*ID], g_WkT[2][LD*R_], g_WvT[2][LD*R_], g_WoT[2][LD*LD];
__device__ bf g_Qh[B_*L_*LD],  g_Ql[B_*L_*LD];
__device__ bf g_Ch[B_*S_*R_],  g_Cl[B_*S_*R_];
__device__ bf g_Kh[B_*S_*LD],  g_Kl[B_*S_*LD];
__device__ bf g_Vth[B_*LD*S_], g_Vtl[B_*LD*S_];
__device__ bf g_Ph[(size_t)B_*H_*L_*S_], g_Pl[(size_t)B_*H_*L_*S_];
__device__ bf g_AOh[B_*L_*LD], g_AOl[B_*L_*LD];
__device__ float g_part[(size_t)B_*H_*L_*32];
__device__ float g_inv[B_*H_*L_];

// ---- helpers ----
__device__ __forceinline__ uint32_t s2u(const void* p){ uint32_t a; asm("{ .reg .u64 t; cvta.to.shared.u64 t, %1; cvt.u32.u64 %0, t; }":"=r"(a):"l"(p)); return a; }
__device__ __forceinline__ void cp16(uint32_t d, const void* g){ asm volatile("cp.async.cg.shared.global [%0],[%1],16;"::"r"(d),"l"(g)); }
#define CP_COMMIT() asm volatile("cp.async.commit_group;":::"memory")
#define CP_WAIT0()  asm volatile("cp.async.wait_group 0;":::"memory")
__device__ __forceinline__ void ldsm4(uint32_t a, uint32_t* r){
    asm volatile("ldmatrix.sync.aligned.m8n8.x4.shared.b16 {%0,%1,%2,%3},[%4];"
        :"=r"(r[0]),"=r"(r[1]),"=r"(r[2]),"=r"(r[3]):"r"(a));
}
__device__ __forceinline__ void ldsm2(uint32_t a, uint32_t* r){
    asm volatile("ldmatrix.sync.aligned.m8n8.x2.shared.b16 {%0,%1},[%2];"
        :"=r"(r[0]),"=r"(r[1]):"r"(a));
}
__device__ __forceinline__ void mma16816(float* c, const uint32_t* a, const uint32_t* b){
    asm volatile("mma.sync.aligned.m16n8k16.row.col.f32.bf16.bf16.f32 "
        "{%0,%1,%2,%3},{%4,%5,%6,%7},{%8,%9},{%0,%1,%2,%3};"
        :"+f"(c[0]),"+f"(c[1]),"+f"(c[2]),"+f"(c[3])
        :"r"(a[0]),"r"(a[1]),"r"(a[2]),"r"(a[3]),"r"(b[0]),"r"(b[1]));
}
__device__ __forceinline__ uint32_t pk(float a, float b){ __nv_bfloat162 t=__floats2bfloat162_rn(a,b); return *(uint32_t*)&t; }
__device__ __forceinline__ void unp(uint32_t u, float&a, float&b){ __nv_bfloat162 t=*(__nv_bfloat162*)&u; a=__bfloat162float(t.x); b=__bfloat162float(t.y); }

// ---- split / transpose converts ----
__global__ __launch_bounds__(256) void split32(const float* __restrict__ in, bf* __restrict__ hi, bf* __restrict__ lo, long n4){
    for(long i = blockIdx.x*256L + threadIdx.x; i < n4; i += (long)gridDim.x*256){
        float4 v = ((const float4*)in)[i];
        float h0=__bfloat162float(__float2bfloat16_rn(v.x)), h1=__bfloat162float(__float2bfloat16_rn(v.y));
        float h2=__bfloat162float(__float2bfloat16_rn(v.z)), h3=__bfloat162float(__float2bfloat16_rn(v.w));
        ((uint2*)hi)[i] = make_uint2(pk(v.x,v.y), pk(v.z,v.w));
        ((uint2*)lo)[i] = make_uint2(pk(v.x-h0,v.y-h1), pk(v.z-h2,v.w-h3));
    }
}
__global__ __launch_bounds__(256) void splitT(const float* __restrict__ W, bf* __restrict__ Th, bf* __restrict__ Tl, int K, int N){
    __shared__ float t[32][33];
    int n0 = blockIdx.x*32, k0 = blockIdx.y*32, tx = threadIdx.x, ty = threadIdx.y;
#pragma unroll
    for(int j=0;j<4;j++) t[ty+j*8][tx] = W[(long)(k0+ty+j*8)*N + n0+tx];
    __syncthreads();
#pragma unroll
    for(int j=0;j<4;j++){
        float v = t[tx][ty+j*8];
        float h = __bfloat162float(__float2bfloat16_rn(v));
        long o = (long)(n0+ty+j*8)*K + k0+tx;
        Th[o] = __float2bfloat16_rn(v); Tl[o] = __float2bfloat16_rn(v-h);
    }
}

// ---- generic split-bf16 HMMA GEMM: C[m,n] = sum_k A[m,k]*B[n,k] ----
struct GP {
    const bf *Ah, *Al; long ldA, zA_b, zA_h;
    const bf *Bh, *Bl; long ldB, zB_b, zB_h;
    int Kc;            // number of 32-wide K chunks
    float* Cf; bf *Chi, *Clo; long ldC, zC_b, zC_h;
    const float *bias, *rbias, *rscale; long rs_z;
    float* part;
    int mode;          // 1 = exp epilogue + row partials
    float scale;
};

template<int NTILE>
__global__ __launch_bounds__(256) void gemm_mma(GP p)
{
    constexpr int WC = (NTILE==128)?4:2, WR = 8/WC;
    constexpr int MW = 128/WR, NW = NTILE/WC;   // warp tile
    constexpr int MI = MW/16,  NI = NW/8;
    constexpr int AHALF = 128*80;               // bytes: one A matrix (hi) per stage
    constexpr int BHALF = NTILE*80;
    constexpr int STAGE = 2*AHALF + 2*BHALF;
    constexpr int AREP = 2, BREP = (NTILE*4)/256;

    extern __shared__ char smc[];
    float* srow = (float*)smc;
    const uint32_t smb = s2u(smc);
    const int tid = threadIdx.x, lane = tid&31, w = tid>>5;
    const int wm = w / WC, wn = w % WC;
    const int quad = lane>>2, qi = lane&3;
    const int z = blockIdx.z;
    const long m0 = (long)blockIdx.y*128, n0 = (long)blockIdx.x*NTILE;

    const long zA = (long)(z>>4)*p.zA_b + (long)(z&15)*p.zA_h;
    const long zB = (long)(z>>4)*p.zB_b + (long)(z&15)*p.zB_h;
    const bf *Ah = p.Ah + zA, *Al = p.Al + zA, *Bh = p.Bh + zB, *Bl = p.Bl + zB;

    if(p.mode==1 && tid < 128) srow[tid] = 0.f;

    auto load_stage = [&](int t, int buf){
        const uint32_t st = smb + 512 + buf*STAGE;
        const long kp = (long)t*32;
#pragma unroll
        for(int rep=0; rep<AREP; rep++){
            int c = tid + rep*256, row = c>>2, cc = c&3;
            uint32_t d = st + row*80 + cc*16;
            const long go = (m0+row)*p.ldA + kp + cc*8;
            cp16(d,         Ah + go);
            cp16(d + AHALF, Al + go);
        }
#pragma unroll
        for(int rep=0; rep<BREP; rep++){
            int c = tid + rep*256, row = c>>2, cc = c&3;
            uint32_t d = st + 2*AHALF + row*80 + cc*16;
            const long go = (n0+row)*p.ldB + kp + cc*8;
            cp16(d,         Bh + go);
            cp16(d + BHALF, Bl + go);
        }
        CP_COMMIT();
    };

    float acc[MI][NI][4];
#pragma unroll
    for(int i=0;i<MI;i++)
#pragma unroll
        for(int j=0;j<NI;j++)
#pragma unroll
            for(int e=0;e<4;e++) acc[i][j][e] = 0.f;

    load_stage(0, 0);

    for(int t = 0; t < p.Kc; t++){
        CP_WAIT0();
        __syncthreads();
        if(t+1 < p.Kc) load_stage(t+1, (t+1)&1);

        const uint32_t st = smb + 512 + (t&1)*STAGE;
        const uint32_t sB = st + 2*AHALF;
#pragma unroll
        for(int ks=0; ks<2; ks++){
            uint32_t ah[MI][4], al[MI][4], bh[NI][2], bl[NI][2];
            {
                const int j = lane>>3, r = lane&7;
#pragma unroll
                for(int mi=0; mi<MI; mi++){
                    int mrow = wm*MW + mi*16 + (j&1)*8 + r;
                    uint32_t a = st + mrow*80 + (ks*2 + (j>>1))*16;
                    ldsm4(a, ah[mi]); ldsm4(a + AHALF, al[mi]);
                }
            }
            {
                const int j = (lane>>3)&1, r = lane&7;
#pragma unroll
                for(int ni=0; ni<NI; ni++){
                    int nrow = wn*NW + ni*8 + r;
                    uint32_t a = sB + nrow*80 + (ks*2 + j)*16;
                    ldsm2(a, bh[ni]); ldsm2(a + BHALF, bl[ni]);
                }
            }
#pragma unroll
            for(int mi=0; mi<MI; mi++)
#pragma unroll
                for(int ni=0; ni<NI; ni++){
                    mma16816(acc[mi][ni], ah[mi], bh[ni]);
                    mma16816(acc[mi][ni], ah[mi], bl[ni]);
                    mma16816(acc[mi][ni], al[mi], bh[ni]);
                }
        }
    }

    // epilogue
    const long zc = (long)(z>>4)*p.zC_b + (long)(z&15)*p.zC_h;
#pragma unroll
    for(int mi=0; mi<MI; mi++){
#pragma unroll
        for(int h=0; h<2; h++){
            const int rl = wm*MW + mi*16 + quad + h*8;
            const long row = m0 + rl;
            const float rs = p.rscale ? p.rscale[(long)z*p.rs_z + row] : 1.f;
            const float rb = p.rbias  ? p.rbias[row] : 0.f;
            float rsum = 0.f;
#pragma unroll
            for(int ni=0; ni<NI; ni++){
                const long col = n0 + wn*NW + ni*8 + qi*2;
                float v0 = acc[mi][ni][2*h]   * rs + rb;
                float v1 = acc[mi][ni][2*h+1] * rs + rb;
                if(p.bias){ v0 += p.bias[col]; v1 += p.bias[col+1]; }
                if(p.mode == 1){
                    v0 = __expf(v0 * p.scale); v1 = __expf(v1 * p.scale);
                    rsum += v0 + v1;
                }
                const long o = zc + row*p.ldC + col;
                if(p.Cf) *(float2*)(p.Cf + o) = make_float2(v0, v1);
                if(p.Chi){
                    float h0 = __bfloat162float(__float2bfloat16_rn(v0));
                    float h1 = __bfloat162float(__float2bfloat16_rn(v1));
                    *(uint32_t*)(p.Chi + o) = pk(v0, v1);
                    *(uint32_t*)(p.Clo + o) = pk(v0-h0, v1-h1);
                }
            }
            if(p.mode == 1) atomicAdd(&srow[rl], rsum);
        }
    }
    if(p.mode == 1){
        __syncthreads();
        if(tid < 128) p.part[((long)z*L_ + m0 + tid)*32 + blockIdx.x] = srow[tid];
    }
}

// ---- normalize: reduce partials -> inv, write fp32 attn weights ----
__global__ __launch_bounds__(256) void norm_k(const bf* __restrict__ Ph, const bf* __restrict__ Pl,
                                              const float* __restrict__ part, float* __restrict__ inv_out,
                                              float* __restrict__ attn)
{
    const long row = blockIdx.x;
    __shared__ float s_inv;
    const int t = threadIdx.x;
    if(t < 32){
        float v = part[row*32 + t];
#pragma unroll
        for(int o=16;o;o>>=1) v += __shfl_xor_sync(0xffffffffu, v, o);
        if(t==0){ s_inv = 1.f/v; inv_out[row] = s_inv; }
    }
    __syncthreads();
    const float inv = s_inv;
    const uint4* ph = (const uint4*)(Ph + row*S_);
    const uint4* pl = (const uint4*)(Pl + row*S_);
    float4* ao = (float4*)(attn + row*(long)S_);
#pragma unroll
    for(int q=0;q<2;q++){
        uint4 hh = ph[t + 256*q], ll = pl[t + 256*q];
        float a0,a1,a2,a3,a4,a5,a6,a7, b0,b1,b2,b3,b4,b5,b6,b7;
        unp(hh.x,a0,a1); unp(hh.y,a2,a3); unp(hh.z,a4,a5); unp(hh.w,a6,a7);
        unp(ll.x,b0,b1); unp(ll.y,b2,b3); unp(ll.z,b4,b5); unp(ll.w,b6,b7);
        long o = (long)(t + 256*q)*2;
        ao[o]   = make_float4((a0+b0)*inv,(a1+b1)*inv,(a2+b2)*inv,(a3+b3)*inv);
        ao[o+1] = make_float4((a4+b4)*inv,(a5+b5)*inv,(a6+b6)*inv,(a7+b7)*inv);
    }
}

// ---- host ----
static inline GP base_gp(){ GP p; memset(&p, 0, sizeof(p)); return p; }

extern "C" void kernel_launch(void* const* d_in, const int* in_sizes, int n_in,
                              void* d_out, int out_size)
{
    const float* latent = (const float*)d_in[0];
    const float* x      = (const float*)d_in[1];
    const float* Wq=(const float*)d_in[2], *bq=(const float*)d_in[3];
    const float* Wc=(const float*)d_in[4], *bc=(const float*)d_in[5];
    const float* Wk=(const float*)d_in[6], *bk=(const float*)d_in[7];
    const float* Wv=(const float*)d_in[8], *bv=(const float*)d_in[9];
    const float* Wo=(const float*)d_in[10],*bo=(const float*)d_in[11];
    float* out  = (float*)d_out;
    float* attn = out + (size_t)B_*L_*LD;

    const int SM128 = 512 + 2*(2*128*80 + 2*128*80);  // 82432
    const int SM64  = 512 + 2*(2*128*80 + 2*64*80);   // 61952
    cudaFuncSetAttribute(gemm_mma<128>, cudaFuncAttributeMaxDynamicSharedMemorySize, SM128);
    cudaFuncSetAttribute(gemm_mma<64>,  cudaFuncAttributeMaxDynamicSharedMemorySize, SM64);

    bf *Lh,*Ll,*Xh,*Xl,*WqT0,*WcT0,*WkT0,*WvT0,*WoT0,*Qh,*Ql,*Ch,*Cl,*Kh,*Kl,*Vth,*Vtl,*Ph,*Pl,*AOh,*AOl;
    float *part,*inv;
    cudaGetSymbolAddress((void**)&Lh,g_Lh);  cudaGetSymbolAddress((void**)&Ll,g_Ll);
    cudaGetSymbolAddress((void**)&Xh,g_Xh);  cudaGetSymbolAddress((void**)&Xl,g_Xl);
    cudaGetSymbolAddress((void**)&WqT0,g_WqT); cudaGetSymbolAddress((void**)&WcT0,g_WcT);
    cudaGetSymbolAddress((void**)&WkT0,g_WkT); cudaGetSymbolAddress((void**)&WvT0,g_WvT);
    cudaGetSymbolAddress((void**)&WoT0,g_WoT);
    cudaGetSymbolAddress((void**)&Qh,g_Qh);  cudaGetSymbolAddress((void**)&Ql,g_Ql);
    cudaGetSymbolAddress((void**)&Ch,g_Ch);  cudaGetSymbolAddress((void**)&Cl,g_Cl);
    cudaGetSymbolAddress((void**)&Kh,g_Kh);  cudaGetSymbolAddress((void**)&Kl,g_Kl);
    cudaGetSymbolAddress((void**)&Vth,g_Vth); cudaGetSymbolAddress((void**)&Vtl,g_Vtl);
    cudaGetSymbolAddress((void**)&Ph,g_Ph);  cudaGetSymbolAddress((void**)&Pl,g_Pl);
    cudaGetSymbolAddress((void**)&AOh,g_AOh); cudaGetSymbolAddress((void**)&AOl,g_AOl);
    cudaGetSymbolAddress((void**)&part,g_part); cudaGetSymbolAddress((void**)&inv,g_inv);

    splitT<<<dim3(LD/32, LD/32), dim3(32,8)>>>(Wq, WqT0, WqT0 + LD*LD, LD, LD);
    splitT<<<dim3(R_/32, ID/32), dim3(32,8)>>>(Wc, WcT0, WcT0 + R_*ID, ID, R_);
    splitT<<<dim3(LD/32, R_/32), dim3(32,8)>>>(Wk, WkT0, WkT0 + LD*R_, R_, LD);
    splitT<<<dim3(LD/32, R_/32), dim3(32,8)>>>(Wv, WvT0, WvT0 + LD*R_, R_, LD);
    splitT<<<dim3(LD/32, LD/32), dim3(32,8)>>>(Wo, WoT0, WoT0 + LD*LD, LD, LD);
    split32<<<2048, 256>>>(latent, Lh, Ll, (long)B_*L_*LD/4);
    split32<<<4096, 256>>>(x, Xh, Xl, (long)B_*S_*ID/4);

    GP p;
    // Q = latent @ Wq + bq
    p = base_gp();
    p.Ah=Lh; p.Al=Ll; p.ldA=LD; p.Bh=WqT0; p.Bl=WqT0+LD*LD; p.ldB=LD; p.Kc=LD/32;
    p.Chi=Qh; p.Clo=Ql; p.ldC=LD; p.bias=bq;
    gemm_mma<128><<<dim3(LD/128, B_*L_/128, 1), 256, SM128>>>(p);
    // compressed = x @ Wc + bc
    p = base_gp();
    p.Ah=Xh; p.Al=Xl; p.ldA=ID; p.Bh=WcT0; p.Bl=WcT0+R_*ID; p.ldB=ID; p.Kc=ID/32;
    p.Chi=Ch; p.Clo=Cl; p.ldC=R_; p.bias=bc;
    gemm_mma<128><<<dim3(R_/128, B_*S_/128, 1), 256, SM128>>>(p);
    // K = comp @ Wk + bk
    p = base_gp();
    p.Ah=Ch; p.Al=Cl; p.ldA=R_; p.Bh=WkT0; p.Bl=WkT0+LD*R_; p.ldB=R_; p.Kc=R_/32;
    p.Chi=Kh; p.Clo=Kl; p.ldC=LD; p.bias=bk;
    gemm_mma<128><<<dim3(LD/128, B_*S_/128, 1), 256, SM128>>>(p);
    // Vt[b, d, s] = Wv^T[d,:] . comp_b[s,:] + bv[d]
    p = base_gp();
    p.Ah=WvT0; p.Al=WvT0+LD*R_; p.ldA=R_;
    p.Bh=Ch; p.Bl=Cl; p.ldB=R_; p.zB_h=(long)S_*R_;
    p.Kc=R_/32; p.Chi=Vth; p.Clo=Vtl; p.ldC=S_; p.zC_h=(long)LD*S_; p.rbias=bv;
    gemm_mma<128><<<dim3(S_/128, LD/128, B_), 256, SM128>>>(p);
    // scores: exp(Q.K/8) unnormalized hi/lo + row partials
    p = base_gp();
    p.Ah=Qh; p.Al=Ql; p.ldA=LD; p.zA_b=(long)L_*LD; p.zA_h=64;
    p.Bh=Kh; p.Bl=Kl; p.ldB=LD; p.zB_b=(long)S_*LD; p.zB_h=64;
    p.Kc=2; p.Chi=Ph; p.Clo=Pl; p.ldC=S_; p.zC_b=(long)H_*L_*S_; p.zC_h=(long)L_*S_;
    p.mode=1; p.scale=0.125f; p.part=part;
    gemm_mma<128><<<dim3(S_/128, L_/128, B_*H_), 256, SM128>>>(p);
    // normalize -> fp32 attn weights + inv
    norm_k<<<B_*H_*L_, 256>>>(Ph, Pl, part, inv, attn);
    // attn_out = (P @ Vt^T) * inv(row)
    p = base_gp();
    p.Ah=Ph; p.Al=Pl; p.ldA=S_; p.zA_b=(long)H_*L_*S_; p.zA_h=(long)L_*S_;
    p.Bh=Vth; p.Bl=Vtl; p.ldB=S_; p.zB_b=(long)LD*S_; p.zB_h=(long)64*S_;
    p.Kc=S_/32; p.Chi=AOh; p.Clo=AOl; p.ldC=LD; p.zC_b=(long)L_*LD; p.zC_h=64;
    p.rscale=inv; p.rs_z=L_;
    gemm_mma<64><<<dim3(1, L_/128, B_*H_), 256, SM64>>>(p);
    // output = AO @ Wo + bo
    p = base_gp();
    p.Ah=AOh; p.Al=AOl; p.ldA=LD; p.Bh=WoT0; p.Bl=WoT0+LD*LD; p.ldB=LD; p.Kc=LD/32;
    p.Cf=out; p.ldC=LD; p.bias=bo;
    gemm_mma<128><<<dim3(LD/128, B_*L_/128, 1), 256, SM128>>>(p);
}

// round 8
// speedup vs baseline: 3.3162x; 1.6990x over previous
#include <cuda_runtime.h>
#include <cuda_fp16.h>
#include <cstdint>
#include <string.h>
#include <math.h>

#define B_  2
#define L_  1024
#define S_  4096
#define H_  16
#define LD  1024
#define ID  2048
#define R_  256

typedef __half hf;

// ---- scratch (device globals, allocation-free) ----
__device__ hf g_Lx[B_*L_*LD];
__device__ hf g_Xx[B_*S_*ID];
__device__ hf g_WqT[LD*LD], g_WcT[R_*ID], g_WkT[LD*R_], g_WvT[LD*R_], g_WoT[LD*LD];
__device__ hf g_Q[B_*L_*LD];
__device__ hf g_C[B_*S_*R_];
__device__ hf g_K[B_*S_*LD];
__device__ hf g_Vt[B_*LD*S_];
__device__ hf g_P[(size_t)B_*H_*L_*S_];
__device__ hf g_AO[B_*L_*LD];
__device__ float g_part[(size_t)B_*H_*L_*32];
__device__ float g_inv[B_*H_*L_];

// ---- helpers ----
__device__ __forceinline__ uint32_t s2u(const void* p){ uint32_t a; asm("{ .reg .u64 t; cvta.to.shared.u64 t, %1; cvt.u32.u64 %0, t; }":"=r"(a):"l"(p)); return a; }
__device__ __forceinline__ void cp16(uint32_t d, const void* g){ asm volatile("cp.async.cg.shared.global [%0],[%1],16;"::"r"(d),"l"(g)); }
#define CP_COMMIT() asm volatile("cp.async.commit_group;":::"memory")
#define CP_WAIT0()  asm volatile("cp.async.wait_group 0;":::"memory")
__device__ __forceinline__ void ldsm4(uint32_t a, uint32_t* r){
    asm volatile("ldmatrix.sync.aligned.m8n8.x4.shared.b16 {%0,%1,%2,%3},[%4];"
        :"=r"(r[0]),"=r"(r[1]),"=r"(r[2]),"=r"(r[3]):"r"(a));
}
__device__ __forceinline__ void ldsm2(uint32_t a, uint32_t* r){
    asm volatile("ldmatrix.sync.aligned.m8n8.x2.shared.b16 {%0,%1},[%2];"
        :"=r"(r[0]),"=r"(r[1]):"r"(a));
}
__device__ __forceinline__ void mma16816(float* c, const uint32_t* a, const uint32_t* b){
    asm volatile("mma.sync.aligned.m16n8k16.row.col.f32.f16.f16.f32 "
        "{%0,%1,%2,%3},{%4,%5,%6,%7},{%8,%9},{%0,%1,%2,%3};"
        :"+f"(c[0]),"+f"(c[1]),"+f"(c[2]),"+f"(c[3])
        :"r"(a[0]),"r"(a[1]),"r"(a[2]),"r"(a[3]),"r"(b[0]),"r"(b[1]));
}
__device__ __forceinline__ uint32_t pkh(float a, float b){ __half2 t=__floats2half2_rn(a,b); return *(uint32_t*)&t; }

// ---- convert kernels ----
__global__ __launch_bounds__(256) void cvt32(const float* __restrict__ in, hf* __restrict__ o, long n4){
    for(long i = blockIdx.x*256L + threadIdx.x; i < n4; i += (long)gridDim.x*256){
        float4 v = ((const float4*)in)[i];
        ((uint2*)o)[i] = make_uint2(pkh(v.x,v.y), pkh(v.z,v.w));
    }
}
__global__ __launch_bounds__(256) void cvtT(const float* __restrict__ W, hf* __restrict__ T, int K, int N){
    __shared__ float t[32][33];
    int n0 = blockIdx.x*32, k0 = blockIdx.y*32, tx = threadIdx.x, ty = threadIdx.y;
#pragma unroll
    for(int j=0;j<4;j++) t[ty+j*8][tx] = W[(long)(k0+ty+j*8)*N + n0+tx];
    __syncthreads();
#pragma unroll
    for(int j=0;j<4;j++)
        T[(long)(n0+ty+j*8)*K + k0+tx] = __float2half_rn(t[tx][ty+j*8]);
}

// ---- generic fp16 HMMA GEMM: C[m,n] = sum_k A[m,k]*B[n,k] ----
struct GP {
    const hf *A; long ldA, zA_b, zA_h;
    const hf *B; long ldB, zB_b, zB_h;
    int Kc;                          // number of 32-wide K chunks
    float* Cf; hf* Ch; long ldC, zC_b, zC_h;
    const float *bias, *rbias, *rscale; long rs_z;
    float* part;
    float* attnW;                    // fused normalized fp32 write of A-tiles (attnv)
    int mode;                        // 1 = exp epilogue + row partials
    float scale;
};

template<int NTILE>
__global__ __launch_bounds__(256) void gemm_mma(GP p)
{
    constexpr int WC = (NTILE==128)?4:2, WR = 8/WC;
    constexpr int MW = 128/WR, NW = NTILE/WC;   // warp tile
    constexpr int MI = MW/16,  NI = NW/8;
    constexpr int ATILE = 128*80;               // bytes per stage (A)
    constexpr int BTILE = NTILE*80;
    constexpr int STAGE = ATILE + BTILE;
    constexpr int AREP = 2, BREP = (NTILE*4)/256;

    extern __shared__ char smc[];
    float* srow = (float*)smc;                  // 512B: row sums (mode1) / inv cache (attnW)
    const uint32_t smb = s2u(smc);
    const int tid = threadIdx.x, lane = tid&31, w = tid>>5;
    const int wm = w / WC, wn = w % WC;
    const int quad = lane>>2, qi = lane&3;
    const int z = blockIdx.z;
    const long m0 = (long)blockIdx.y*128, n0 = (long)blockIdx.x*NTILE;

    const long zA = (long)(z>>4)*p.zA_b + (long)(z&15)*p.zA_h;
    const long zB = (long)(z>>4)*p.zB_b + (long)(z&15)*p.zB_h;
    const hf *A = p.A + zA, *B = p.B + zB;
    const long zAttn = (long)z*L_*S_;

    if(p.mode==1 && tid < 128) srow[tid] = 0.f;
    if(p.attnW && tid < 128) srow[tid] = p.rscale[(long)z*p.rs_z + m0 + tid];

    auto load_stage = [&](int t, int buf){
        const uint32_t st = smb + 512 + buf*STAGE;
        const long kp = (long)t*32;
#pragma unroll
        for(int rep=0; rep<AREP; rep++){
            int c = tid + rep*256, row = c>>2, cc = c&3;
            cp16(st + row*80 + cc*16, A + (m0+row)*p.ldA + kp + cc*8);
        }
#pragma unroll
        for(int rep=0; rep<BREP; rep++){
            int c = tid + rep*256, row = c>>2, cc = c&3;
            cp16(st + ATILE + row*80 + cc*16, B + (n0+row)*p.ldB + kp + cc*8);
        }
        CP_COMMIT();
    };

    float acc[MI][NI][4];
#pragma unroll
    for(int i=0;i<MI;i++)
#pragma unroll
        for(int j=0;j<NI;j++)
#pragma unroll
            for(int e=0;e<4;e++) acc[i][j][e] = 0.f;

    load_stage(0, 0);

    for(int t = 0; t < p.Kc; t++){
        CP_WAIT0();
        __syncthreads();
        if(t+1 < p.Kc) load_stage(t+1, (t+1)&1);

        const uint32_t st = smb + 512 + (t&1)*STAGE;
        const uint32_t sB = st + ATILE;

        if(p.attnW){   // fused normalized attn write: each A (P) element passes here once
            const long kp = (long)t*32;
#pragma unroll
            for(int rep=0; rep<AREP; rep++){
                int c = tid + rep*256, row = c>>2, cc = c&3;
                uint4 v = *(uint4*)(smc + 512 + (t&1)*STAGE + row*80 + cc*16);
                float iv = srow[row];
                __half2* hp = (__half2*)&v;
                float2 f0=__half22float2(hp[0]), f1=__half22float2(hp[1]);
                float2 f2=__half22float2(hp[2]), f3=__half22float2(hp[3]);
                float* dst = p.attnW + zAttn + (m0+row)*(long)S_ + kp + cc*8;
                *(float4*)dst     = make_float4(f0.x*iv,f0.y*iv,f1.x*iv,f1.y*iv);
                *(float4*)(dst+4) = make_float4(f2.x*iv,f2.y*iv,f3.x*iv,f3.y*iv);
            }
        }

#pragma unroll
        for(int ks=0; ks<2; ks++){
            uint32_t af[MI][4], bfr[NI][2];
            {
                const int j = lane>>3, r = lane&7;
#pragma unroll
                for(int mi=0; mi<MI; mi++){
                    int mrow = wm*MW + mi*16 + (j&1)*8 + r;
                    ldsm4(st + mrow*80 + (ks*2 + (j>>1))*16, af[mi]);
                }
            }
            {
                const int j = (lane>>3)&1, r = lane&7;
#pragma unroll
                for(int ni=0; ni<NI; ni++){
                    int nrow = wn*NW + ni*8 + r;
                    ldsm2(sB + nrow*80 + (ks*2 + j)*16, bfr[ni]);
                }
            }
#pragma unroll
            for(int mi=0; mi<MI; mi++)
#pragma unroll
                for(int ni=0; ni<NI; ni++)
                    mma16816(acc[mi][ni], af[mi], bfr[ni]);
        }
    }

    // epilogue
    const long zc = (long)(z>>4)*p.zC_b + (long)(z&15)*p.zC_h;
#pragma unroll
    for(int mi=0; mi<MI; mi++){
#pragma unroll
        for(int h=0; h<2; h++){
            const int rl = wm*MW + mi*16 + quad + h*8;
            const long row = m0 + rl;
            const float rs = p.rscale ? p.rscale[(long)z*p.rs_z + row] : 1.f;
            const float rb = p.rbias  ? p.rbias[row] : 0.f;
            float rsum = 0.f;
#pragma unroll
            for(int ni=0; ni<NI; ni++){
                const long col = n0 + wn*NW + ni*8 + qi*2;
                float v0 = acc[mi][ni][2*h]   * rs + rb;
                float v1 = acc[mi][ni][2*h+1] * rs + rb;
                if(p.bias){ v0 += p.bias[col]; v1 += p.bias[col+1]; }
                if(p.mode == 1){
                    v0 = exp2f(v0 * p.scale); v1 = exp2f(v1 * p.scale);
                    rsum += v0 + v1;
                }
                const long o = zc + row*p.ldC + col;
                if(p.Cf) *(float2*)(p.Cf + o) = make_float2(v0, v1);
                if(p.Ch) *(uint32_t*)(p.Ch + o) = pkh(v0, v1);
            }
            if(p.mode == 1) atomicAdd(&srow[rl], rsum);
        }
    }
    if(p.mode == 1){
        __syncthreads();
        if(tid < 128) p.part[((long)z*L_ + m0 + tid)*32 + blockIdx.x] = srow[tid];
    }
}

// ---- reduce partials -> inv row sums ----
__global__ __launch_bounds__(256) void red_inv(const float* __restrict__ part, float* __restrict__ inv){
    const long row = blockIdx.x*8 + (threadIdx.x>>5);
    const int lane = threadIdx.x&31;
    float v = part[row*32 + lane];
#pragma unroll
    for(int o=16;o;o>>=1) v += __shfl_xor_sync(0xffffffffu, v, o);
    if(lane==0) inv[row] = 1.f/v;
}

// ---- host ----
static inline GP base_gp(){ GP p; memset(&p, 0, sizeof(p)); return p; }

extern "C" void kernel_launch(void* const* d_in, const int* in_sizes, int n_in,
                              void* d_out, int out_size)
{
    const float* latent = (const float*)d_in[0];
    const float* x      = (const float*)d_in[1];
    const float* Wq=(const float*)d_in[2], *bq=(const float*)d_in[3];
    const float* Wc=(const float*)d_in[4], *bc=(const float*)d_in[5];
    const float* Wk=(const float*)d_in[6], *bk=(const float*)d_in[7];
    const float* Wv=(const float*)d_in[8], *bv=(const float*)d_in[9];
    const float* Wo=(const float*)d_in[10],*bo=(const float*)d_in[11];
    float* out  = (float*)d_out;
    float* attn = out + (size_t)B_*L_*LD;

    const int SM128 = 512 + 2*(128*80 + 128*80);  // 41472
    const int SM64  = 512 + 2*(128*80 + 64*80);   // 31232
    cudaFuncSetAttribute(gemm_mma<128>, cudaFuncAttributeMaxDynamicSharedMemorySize, SM128);
    cudaFuncSetAttribute(gemm_mma<64>,  cudaFuncAttributeMaxDynamicSharedMemorySize, SM64);

    hf *Lx,*Xx,*WqT,*WcT,*WkT,*WvT,*WoT,*Q,*C,*K,*Vt,*P,*AO;
    float *part,*inv;
    cudaGetSymbolAddress((void**)&Lx,g_Lx);   cudaGetSymbolAddress((void**)&Xx,g_Xx);
    cudaGetSymbolAddress((void**)&WqT,g_WqT); cudaGetSymbolAddress((void**)&WcT,g_WcT);
    cudaGetSymbolAddress((void**)&WkT,g_WkT); cudaGetSymbolAddress((void**)&WvT,g_WvT);
    cudaGetSymbolAddress((void**)&WoT,g_WoT);
    cudaGetSymbolAddress((void**)&Q,g_Q);     cudaGetSymbolAddress((void**)&C,g_C);
    cudaGetSymbolAddress((void**)&K,g_K);     cudaGetSymbolAddress((void**)&Vt,g_Vt);
    cudaGetSymbolAddress((void**)&P,g_P);     cudaGetSymbolAddress((void**)&AO,g_AO);
    cudaGetSymbolAddress((void**)&part,g_part); cudaGetSymbolAddress((void**)&inv,g_inv);

    cvtT<<<dim3(LD/32, LD/32), dim3(32,8)>>>(Wq, WqT, LD, LD);
    cvtT<<<dim3(R_/32, ID/32), dim3(32,8)>>>(Wc, WcT, ID, R_);
    cvtT<<<dim3(LD/32, R_/32), dim3(32,8)>>>(Wk, WkT, R_, LD);
    cvtT<<<dim3(LD/32, R_/32), dim3(32,8)>>>(Wv, WvT, R_, LD);
    cvtT<<<dim3(LD/32, LD/32), dim3(32,8)>>>(Wo, WoT, LD, LD);
    cvt32<<<2048, 256>>>(latent, Lx, (long)B_*L_*LD/4);
    cvt32<<<4096, 256>>>(x, Xx, (long)B_*S_*ID/4);

    GP p;
    // Q = latent @ Wq + bq
    p = base_gp();
    p.A=Lx; p.ldA=LD; p.B=WqT; p.ldB=LD; p.Kc=LD/32;
    p.Ch=Q; p.ldC=LD; p.bias=bq;
    gemm_mma<128><<<dim3(LD/128, B_*L_/128, 1), 256, SM128>>>(p);
    // compressed = x @ Wc + bc
    p = base_gp();
    p.A=Xx; p.ldA=ID; p.B=WcT; p.ldB=ID; p.Kc=ID/32;
    p.Ch=C; p.ldC=R_; p.bias=bc;
    gemm_mma<128><<<dim3(R_/128, B_*S_/128, 1), 256, SM128>>>(p);
    // K = comp @ Wk + bk
    p = base_gp();
    p.A=C; p.ldA=R_; p.B=WkT; p.ldB=R_; p.Kc=R_/32;
    p.Ch=K; p.ldC=LD; p.bias=bk;
    gemm_mma<128><<<dim3(LD/128, B_*S_/128, 1), 256, SM128>>>(p);
    // Vt[b, d, s] = Wv^T[d,:] . comp_b[s,:] + bv[d]
    p = base_gp();
    p.A=WvT; p.ldA=R_;
    p.B=C; p.ldB=R_; p.zB_h=(long)S_*R_;
    p.Kc=R_/32; p.Ch=Vt; p.ldC=S_; p.zC_h=(long)LD*S_; p.rbias=bv;
    gemm_mma<128><<<dim3(S_/128, LD/128, B_), 256, SM128>>>(p);
    // scores: P = exp(Q.K/8) unnormalized fp16 + row partial sums
    p = base_gp();
    p.A=Q; p.ldA=LD; p.zA_b=(long)L_*LD; p.zA_h=64;
    p.B=K; p.ldB=LD; p.zB_b=(long)S_*LD; p.zB_h=64;
    p.Kc=2; p.Ch=P; p.ldC=S_; p.zC_b=(long)H_*L_*S_; p.zC_h=(long)L_*S_;
    p.mode=1; p.scale=0.125f*1.44269504088896340736f; p.part=part;
    gemm_mma<128><<<dim3(S_/128, L_/128, B_*H_), 256, SM128>>>(p);
    // reduce partials -> 1/rowsum
    red_inv<<<(B_*H_*L_)/8, 256>>>(part, inv);
    // attn_out = (P @ Vt^T) * inv(row); fused: writes normalized fp32 attn weights
    p = base_gp();
    p.A=P; p.ldA=S_; p.zA_b=(long)H_*L_*S_; p.zA_h=(long)L_*S_;
    p.B=Vt; p.ldB=S_; p.zB_b=(long)LD*S_; p.zB_h=(long)64*S_;
    p.Kc=S_/32; p.Ch=AO; p.ldC=LD; p.zC_b=(long)L_*LD; p.zC_h=64;
    p.rscale=inv; p.rs_z=L_; p.attnW=attn;
    gemm_mma<64><<<dim3(1, L_/128, B_*H_), 256, SM64>>>(p);
    // output = AO @ Wo + bo
    p = base_gp();
    p.A=AO; p.ldA=LD; p.B=WoT; p.ldB=LD; p.Kc=LD/32;
    p.Cf=out; p.ldC=LD; p.bias=bo;
    gemm_mma<128><<<dim3(LD/128, B_*L_/128, 1), 256, SM128>>>(p);
}

// round 11
// speedup vs baseline: 3.3181x; 1.0006x over previous
#include <cuda_runtime.h>
#include <cuda_fp16.h>
#include <cstdint>
#include <string.h>
#include <math.h>

#define B_  2
#define L_  1024
#define S_  4096
#define H_  16
#define LD  1024
#define ID  2048
#define R_  256

typedef __half hf;

// ---- scratch (device globals, allocation-free) ----
__device__ hf g_Lx[B_*L_*LD];
__device__ hf g_Xx[B_*S_*ID];
__device__ hf g_WqT[LD*LD], g_WcT[R_*ID], g_WkT[LD*R_], g_WvT[LD*R_], g_WoT[LD*LD];
__device__ hf g_Q[B_*L_*LD];
__device__ hf g_C[B_*S_*R_];
__device__ hf g_K[B_*S_*LD];
__device__ hf g_Vt[B_*LD*S_];
__device__ hf g_P[(size_t)B_*H_*L_*S_];
__device__ hf g_AO[B_*L_*LD];
__device__ float g_part[(size_t)B_*H_*L_*32];
__device__ float g_inv[B_*H_*L_];

// ---- helpers ----
__device__ __forceinline__ uint32_t s2u(const void* p){ uint32_t a; asm("{ .reg .u64 t; cvta.to.shared.u64 t, %1; cvt.u32.u64 %0, t; }":"=r"(a):"l"(p)); return a; }
__device__ __forceinline__ void cp16(uint32_t d, const void* g){ asm volatile("cp.async.cg.shared.global [%0],[%1],16;"::"r"(d),"l"(g)); }
#define CP_COMMIT() asm volatile("cp.async.commit_group;":::"memory")
#define CP_WAIT0()  asm volatile("cp.async.wait_group 0;":::"memory")
#define CP_WAIT1()  asm volatile("cp.async.wait_group 1;":::"memory")
__device__ __forceinline__ void ldsm4(uint32_t a, uint32_t* r){
    asm volatile("ldmatrix.sync.aligned.m8n8.x4.shared.b16 {%0,%1,%2,%3},[%4];"
        :"=r"(r[0]),"=r"(r[1]),"=r"(r[2]),"=r"(r[3]):"r"(a));
}
__device__ __forceinline__ void ldsm2(uint32_t a, uint32_t* r){
    asm volatile("ldmatrix.sync.aligned.m8n8.x2.shared.b16 {%0,%1},[%2];"
        :"=r"(r[0]),"=r"(r[1]):"r"(a));
}
__device__ __forceinline__ void mma16816(float* c, const uint32_t* a, const uint32_t* b){
    asm volatile("mma.sync.aligned.m16n8k16.row.col.f32.f16.f16.f32 "
        "{%0,%1,%2,%3},{%4,%5,%6,%7},{%8,%9},{%0,%1,%2,%3};"
        :"+f"(c[0]),"+f"(c[1]),"+f"(c[2]),"+f"(c[3])
        :"r"(a[0]),"r"(a[1]),"r"(a[2]),"r"(a[3]),"r"(b[0]),"r"(b[1]));
}
__device__ __forceinline__ uint32_t pkh(float a, float b){ __half2 t=__floats2half2_rn(a,b); return *(uint32_t*)&t; }

// ---- fused activation convert: latent + x in one launch ----
__global__ __launch_bounds__(256) void cvtA(const float* __restrict__ lat, const float* __restrict__ x,
                                            hf* __restrict__ Lx, hf* __restrict__ Xx, long nL, long nT){
    for(long i = blockIdx.x*256L + threadIdx.x; i < nT; i += (long)gridDim.x*256){
        const float4 v = (i < nL) ? ((const float4*)lat)[i] : ((const float4*)x)[i - nL];
        uint2 o = make_uint2(pkh(v.x,v.y), pkh(v.z,v.w));
        if(i < nL) ((uint2*)Lx)[i] = o; else ((uint2*)Xx)[i - nL] = o;
    }
}
// ---- fused weight transpose-convert: 5 weights, z-selected ----
struct WT5 { const float* W[5]; hf* T[5]; int K[5], N[5]; };
__global__ __launch_bounds__(256) void cvtW(WT5 w){
    const int wi = blockIdx.z;
    const int K = w.K[wi], N = w.N[wi];
    const int n0 = blockIdx.x*32, k0 = blockIdx.y*32;
    if(n0 >= N || k0 >= K) return;
    __shared__ float t[32][33];
    const float* W = w.W[wi]; hf* T = w.T[wi];
    int tx = threadIdx.x, ty = threadIdx.y;
#pragma unroll
    for(int j=0;j<4;j++) t[ty+j*8][tx] = W[(long)(k0+ty+j*8)*N + n0+tx];
    __syncthreads();
#pragma unroll
    for(int j=0;j<4;j++)
        T[(long)(n0+ty+j*8)*K + k0+tx] = __float2half_rn(t[tx][ty+j*8]);
}

// ---- generic fp16 HMMA GEMM: C[m,n] = sum_k A[m,k]*B[n,k] ----
struct GP {
    const hf *A; long ldA, zA_b, zA_h;
    const hf *B; long ldB, zB_b, zB_h;
    int Kc;                          // number of 32-wide K chunks
    float* Cf; hf* Ch; long ldC, zC_b, zC_h;
    const float *bias, *rbias, *rscale; long rs_z;
    float* part;
    float* attnW;                    // fused normalized fp32 write of A-tiles (attnv)
    int mode;                        // 1 = exp epilogue + row partials
    float scale;
};

template<int NTILE>
__global__ __launch_bounds__(256) void gemm_mma(GP p)
{
    constexpr int WC = (NTILE==128)?4:2, WR = 8/WC;
    constexpr int MW = 128/WR, NW = NTILE/WC;   // warp tile
    constexpr int MI = MW/16,  NI = NW/8;
    constexpr int ATILE = 128*80;               // bytes per stage (A)
    constexpr int BTILE = NTILE*80;
    constexpr int STAGE = ATILE + BTILE;
    constexpr int AREP = 2, BREP = (NTILE*4)/256;

    extern __shared__ char smc[];
    float* srow = (float*)smc;                  // 512B: row sums (mode1) / inv cache (attnW)
    const uint32_t smb = s2u(smc);
    const int tid = threadIdx.x, lane = tid&31, w = tid>>5;
    const int wm = w / WC, wn = w % WC;
    const int quad = lane>>2, qi = lane&3;
    const int z = blockIdx.z;
    const long m0 = (long)blockIdx.y*128, n0 = (long)blockIdx.x*NTILE;

    const long zA = (long)(z>>4)*p.zA_b + (long)(z&15)*p.zA_h;
    const long zB = (long)(z>>4)*p.zB_b + (long)(z&15)*p.zB_h;
    const hf *A = p.A + zA, *B = p.B + zB;
    const long zAttn = (long)z*L_*S_;

    if(p.mode==1 && tid < 128) srow[tid] = 0.f;
    if(p.attnW && tid < 128) srow[tid] = p.rscale[(long)z*p.rs_z + m0 + tid];

    auto load_stage = [&](int t, int buf){
        const uint32_t st = smb + 512 + buf*STAGE;
        const long kp = (long)t*32;
#pragma unroll
        for(int rep=0; rep<AREP; rep++){
            int c = tid + rep*256, row = c>>2, cc = c&3;
            cp16(st + row*80 + cc*16, A + (m0+row)*p.ldA + kp + cc*8);
        }
#pragma unroll
        for(int rep=0; rep<BREP; rep++){
            int c = tid + rep*256, row = c>>2, cc = c&3;
            cp16(st + ATILE + row*80 + cc*16, B + (n0+row)*p.ldB + kp + cc*8);
        }
        CP_COMMIT();
    };

    float acc[MI][NI][4];
#pragma unroll
    for(int i=0;i<MI;i++)
#pragma unroll
        for(int j=0;j<NI;j++)
#pragma unroll
            for(int e=0;e<4;e++) acc[i][j][e] = 0.f;

    // 3-stage pipeline
    load_stage(0, 0);
    if(p.Kc > 1) load_stage(1, 1);

    for(int t = 0; t < p.Kc; t++){
        if(t+2 < p.Kc) { CP_WAIT1(); } else { CP_WAIT0(); }
        __syncthreads();
        if(t+2 < p.Kc) load_stage(t+2, (t+2)%3);

        const int buf = t%3;
        const uint32_t st = smb + 512 + buf*STAGE;
        const uint32_t sB = st + ATILE;

        if(p.attnW){   // fused normalized attn write: each A (P) element passes here once
            const long kp = (long)t*32;
#pragma unroll
            for(int rep=0; rep<AREP; rep++){
                int c = tid + rep*256, row = c>>2, cc = c&3;
                uint4 v = *(uint4*)(smc + 512 + buf*STAGE + row*80 + cc*16);
                float iv = srow[row];
                __half2* hp = (__half2*)&v;
                float2 f0=__half22float2(hp[0]), f1=__half22float2(hp[1]);
                float2 f2=__half22float2(hp[2]), f3=__half22float2(hp[3]);
                float* dst = p.attnW + zAttn + (m0+row)*(long)S_ + kp + cc*8;
                *(float4*)dst     = make_float4(f0.x*iv,f0.y*iv,f1.x*iv,f1.y*iv);
                *(float4*)(dst+4) = make_float4(f2.x*iv,f2.y*iv,f3.x*iv,f3.y*iv);
            }
        }

#pragma unroll
        for(int ks=0; ks<2; ks++){
            uint32_t af[MI][4], bfr[NI][2];
            {
                const int j = lane>>3, r = lane&7;
#pragma unroll
                for(int mi=0; mi<MI; mi++){
                    int mrow = wm*MW + mi*16 + (j&1)*8 + r;
                    ldsm4(st + mrow*80 + (ks*2 + (j>>1))*16, af[mi]);
                }
            }
            {
                const int j = (lane>>3)&1, r = lane&7;
#pragma unroll
                for(int ni=0; ni<NI; ni++){
                    int nrow = wn*NW + ni*8 + r;
                    ldsm2(sB + nrow*80 + (ks*2 + j)*16, bfr[ni]);
                }
            }
#pragma unroll
            for(int mi=0; mi<MI; mi++)
#pragma unroll
                for(int ni=0; ni<NI; ni++)
                    mma16816(acc[mi][ni], af[mi], bfr[ni]);
        }
    }

    // epilogue
    const long zc = (long)(z>>4)*p.zC_b + (long)(z&15)*p.zC_h;
#pragma unroll
    for(int mi=0; mi<MI; mi++){
#pragma unroll
        for(int h=0; h<2; h++){
            const int rl = wm*MW + mi*16 + quad + h*8;
            const long row = m0 + rl;
            const float rs = p.rscale ? p.rscale[(long)z*p.rs_z + row] : 1.f;
            const float rb = p.rbias  ? p.rbias[row] : 0.f;
            float rsum = 0.f;
#pragma unroll
            for(int ni=0; ni<NI; ni++){
                const long col = n0 + wn*NW + ni*8 + qi*2;
                float v0 = acc[mi][ni][2*h]   * rs + rb;
                float v1 = acc[mi][ni][2*h+1] * rs + rb;
                if(p.bias){ v0 += p.bias[col]; v1 += p.bias[col+1]; }
                if(p.mode == 1){
                    v0 = exp2f(v0 * p.scale); v1 = exp2f(v1 * p.scale);
                    rsum += v0 + v1;
                }
                const long o = zc + row*p.ldC + col;
                if(p.Cf) *(float2*)(p.Cf + o) = make_float2(v0, v1);
                if(p.Ch) *(uint32_t*)(p.Ch + o) = pkh(v0, v1);
            }
            if(p.mode == 1) atomicAdd(&srow[rl], rsum);
        }
    }
    if(p.mode == 1){
        __syncthreads();
        if(tid < 128) p.part[((long)z*L_ + m0 + tid)*32 + blockIdx.x] = srow[tid];
    }
}

// ---- reduce partials -> inv row sums ----
__global__ __launch_bounds__(256) void red_inv(const float* __restrict__ part, float* __restrict__ inv){
    const long row = blockIdx.x*8 + (threadIdx.x>>5);
    const int lane = threadIdx.x&31;
    float v = part[row*32 + lane];
#pragma unroll
    for(int o=16;o;o>>=1) v += __shfl_xor_sync(0xffffffffu, v, o);
    if(lane==0) inv[row] = 1.f/v;
}

// ---- host ----
static inline GP base_gp(){ GP p; memset(&p, 0, sizeof(p)); return p; }

extern "C" void kernel_launch(void* const* d_in, const int* in_sizes, int n_in,
                              void* d_out, int out_size)
{
    const float* latent = (const float*)d_in[0];
    const float* x      = (const float*)d_in[1];
    const float* Wq=(const float*)d_in[2], *bq=(const float*)d_in[3];
    const float* Wc=(const float*)d_in[4], *bc=(const float*)d_in[5];
    const float* Wk=(const float*)d_in[6], *bk=(const float*)d_in[7];
    const float* Wv=(const float*)d_in[8], *bv=(const float*)d_in[9];
    const float* Wo=(const float*)d_in[10],*bo=(const float*)d_in[11];
    float* out  = (float*)d_out;
    float* attn = out + (size_t)B_*L_*LD;

    const int SM128 = 512 + 3*(128*80 + 128*80);  // 61952
    const int SM64  = 512 + 3*(128*80 + 64*80);   // 46592
    cudaFuncSetAttribute(gemm_mma<128>, cudaFuncAttributeMaxDynamicSharedMemorySize, SM128);
    cudaFuncSetAttribute(gemm_mma<64>,  cudaFuncAttributeMaxDynamicSharedMemorySize, SM64);

    hf *Lx,*Xx,*WqT,*WcT,*WkT,*WvT,*WoT,*Q,*C,*K,*Vt,*P,*AO;
    float *part,*inv;
    cudaGetSymbolAddress((void**)&Lx,g_Lx);   cudaGetSymbolAddress((void**)&Xx,g_Xx);
    cudaGetSymbolAddress((void**)&WqT,g_WqT); cudaGetSymbolAddress((void**)&WcT,g_WcT);
    cudaGetSymbolAddress((void**)&WkT,g_WkT); cudaGetSymbolAddress((void**)&WvT,g_WvT);
    cudaGetSymbolAddress((void**)&WoT,g_WoT);
    cudaGetSymbolAddress((void**)&Q,g_Q);     cudaGetSymbolAddress((void**)&C,g_C);
    cudaGetSymbolAddress((void**)&K,g_K);     cudaGetSymbolAddress((void**)&Vt,g_Vt);
    cudaGetSymbolAddress((void**)&P,g_P);     cudaGetSymbolAddress((void**)&AO,g_AO);
    cudaGetSymbolAddress((void**)&part,g_part); cudaGetSymbolAddress((void**)&inv,g_inv);

    // fused converts: weights (z = 0..4), activations (one kernel)
    WT5 wt;
    wt.W[0]=Wq; wt.T[0]=WqT; wt.K[0]=LD; wt.N[0]=LD;
    wt.W[1]=Wc; wt.T[1]=WcT; wt.K[1]=ID; wt.N[1]=R_;
    wt.W[2]=Wk; wt.T[2]=WkT; wt.K[2]=R_; wt.N[2]=LD;
    wt.W[3]=Wv; wt.T[3]=WvT; wt.K[3]=R_; wt.N[3]=LD;
    wt.W[4]=Wo; wt.T[4]=WoT; wt.K[4]=LD; wt.N[4]=LD;
    cvtW<<<dim3(32, 64, 5), dim3(32,8)>>>(wt);
    const long nL = (long)B_*L_*LD/4, nX = (long)B_*S_*ID/4;
    cvtA<<<4096, 256>>>(latent, x, Lx, Xx, nL, nL + nX);

    GP p;
    // Q = latent @ Wq + bq   (NTILE=64 -> 256 CTAs)
    p = base_gp();
    p.A=Lx; p.ldA=LD; p.B=WqT; p.ldB=LD; p.Kc=LD/32;
    p.Ch=Q; p.ldC=LD; p.bias=bq;
    gemm_mma<64><<<dim3(LD/64, B_*L_/128, 1), 256, SM64>>>(p);
    // compressed = x @ Wc + bc  (NTILE=64 -> 256 CTAs)
    p = base_gp();
    p.A=Xx; p.ldA=ID; p.B=WcT; p.ldB=ID; p.Kc=ID/32;
    p.Ch=C; p.ldC=R_; p.bias=bc;
    gemm_mma<64><<<dim3(R_/64, B_*S_/128, 1), 256, SM64>>>(p);
    // K = comp @ Wk + bk
    p = base_gp();
    p.A=C; p.ldA=R_; p.B=WkT; p.ldB=R_; p.Kc=R_/32;
    p.Ch=K; p.ldC=LD; p.bias=bk;
    gemm_mma<128><<<dim3(LD/128, B_*S_/128, 1), 256, SM128>>>(p);
    // Vt[b, d, s] = Wv^T[d,:] . comp_b[s,:] + bv[d]
    p = base_gp();
    p.A=WvT; p.ldA=R_;
    p.B=C; p.ldB=R_; p.zB_h=(long)S_*R_;
    p.Kc=R_/32; p.Ch=Vt; p.ldC=S_; p.zC_h=(long)LD*S_; p.rbias=bv;
    gemm_mma<128><<<dim3(S_/128, LD/128, B_), 256, SM128>>>(p);
    // scores: P = exp(Q.K/8) unnormalized fp16 + row partial sums
    p = base_gp();
    p.A=Q; p.ldA=LD; p.zA_b=(long)L_*LD; p.zA_h=64;
    p.B=K; p.ldB=LD; p.zB_b=(long)S_*LD; p.zB_h=64;
    p.Kc=2; p.Ch=P; p.ldC=S_; p.zC_b=(long)H_*L_*S_; p.zC_h=(long)L_*S_;
    p.mode=1; p.scale=0.125f*1.44269504088896340736f; p.part=part;
    gemm_mma<128><<<dim3(S_/128, L_/128, B_*H_), 256, SM128>>>(p);
    // reduce partials -> 1/rowsum
    red_inv<<<(B_*H_*L_)/8, 256>>>(part, inv);
    // attn_out = (P @ Vt^T) * inv(row); fused: writes normalized fp32 attn weights
    p = base_gp();
    p.A=P; p.ldA=S_; p.zA_b=(long)H_*L_*S_; p.zA_h=(long)L_*S_;
    p.B=Vt; p.ldB=S_; p.zB_b=(long)LD*S_; p.zB_h=(long)64*S_;
    p.Kc=S_/32; p.Ch=AO; p.ldC=LD; p.zC_b=(long)L_*LD; p.zC_h=64;
    p.rscale=inv; p.rs_z=L_; p.attnW=attn;
    gemm_mma<64><<<dim3(1, L_/128, B_*H_), 256, SM64>>>(p);
    // output = AO @ Wo + bo  (NTILE=64 -> 256 CTAs)
    p = base_gp();
    p.A=AO; p.ldA=LD; p.B=WoT; p.ldB=LD; p.Kc=LD/32;
    p.Cf=out; p.ldC=LD; p.bias=bo;
    gemm_mma<64><<<dim3(LD/64, B_*L_/128, 1), 256, SM64>>>(p);
}

// round 12
// speedup vs baseline: 3.5930x; 1.0828x over previous
#include <cuda_runtime.h>
#include <cuda_fp16.h>
#include <cstdint>
#include <string.h>
#include <math.h>

#define B_  2
#define L_  1024
#define S_  4096
#define H_  16
#define LD  1024
#define ID  2048
#define R_  256

typedef __half hf;

// ---- scratch (device globals, allocation-free) ----
__device__ hf g_Lx[B_*L_*LD];
__device__ hf g_Xx[B_*S_*ID];
__device__ hf g_WqT[LD*LD], g_WcT[R_*ID], g_WkT[LD*R_], g_WvT[LD*R_], g_WoT[LD*LD];
__device__ hf g_Q[B_*L_*LD];
__device__ hf g_C[B_*S_*R_];
__device__ hf g_K[B_*S_*LD];
__device__ hf g_Vt[B_*LD*S_];
__device__ hf g_P[(size_t)B_*H_*L_*S_];
__device__ hf g_AO[B_*L_*LD];
__device__ float g_part[(size_t)B_*H_*L_*32];
__device__ float g_inv[B_*H_*L_];

// ---- helpers ----
__device__ __forceinline__ uint32_t s2u(const void* p){ uint32_t a; asm("{ .reg .u64 t; cvta.to.shared.u64 t, %1; cvt.u32.u64 %0, t; }":"=r"(a):"l"(p)); return a; }
__device__ __forceinline__ void cp16(uint32_t d, const void* g){ asm volatile("cp.async.cg.shared.global [%0],[%1],16;"::"r"(d),"l"(g)); }
#define CP_COMMIT() asm volatile("cp.async.commit_group;":::"memory")
#define CP_WAIT0()  asm volatile("cp.async.wait_group 0;":::"memory")
#define CP_WAIT1()  asm volatile("cp.async.wait_group 1;":::"memory")
__device__ __forceinline__ void ldsm4(uint32_t a, uint32_t* r){
    asm volatile("ldmatrix.sync.aligned.m8n8.x4.shared.b16 {%0,%1,%2,%3},[%4];"
        :"=r"(r[0]),"=r"(r[1]),"=r"(r[2]),"=r"(r[3]):"r"(a));
}
__device__ __forceinline__ void ldsm2(uint32_t a, uint32_t* r){
    asm volatile("ldmatrix.sync.aligned.m8n8.x2.shared.b16 {%0,%1},[%2];"
        :"=r"(r[0]),"=r"(r[1]):"r"(a));
}
__device__ __forceinline__ void mma16816(float* c, const uint32_t* a, const uint32_t* b){
    asm volatile("mma.sync.aligned.m16n8k16.row.col.f32.f16.f16.f32 "
        "{%0,%1,%2,%3},{%4,%5,%6,%7},{%8,%9},{%0,%1,%2,%3};"
        :"+f"(c[0]),"+f"(c[1]),"+f"(c[2]),"+f"(c[3])
        :"r"(a[0]),"r"(a[1]),"r"(a[2]),"r"(a[3]),"r"(b[0]),"r"(b[1]));
}
__device__ __forceinline__ uint32_t pkh(float a, float b){ __half2 t=__floats2half2_rn(a,b); return *(uint32_t*)&t; }

// ---- fused activation convert: latent + x in one launch ----
__global__ __launch_bounds__(256) void cvtA(const float* __restrict__ lat, const float* __restrict__ x,
                                            hf* __restrict__ Lx, hf* __restrict__ Xx, long nL, long nT){
    for(long i = blockIdx.x*256L + threadIdx.x; i < nT; i += (long)gridDim.x*256){
        const float4 v = (i < nL) ? ((const float4*)lat)[i] : ((const float4*)x)[i - nL];
        uint2 o = make_uint2(pkh(v.x,v.y), pkh(v.z,v.w));
        if(i < nL) ((uint2*)Lx)[i] = o; else ((uint2*)Xx)[i - nL] = o;
    }
}
// ---- fused weight transpose-convert: 5 weights, z-selected ----
struct WT5 { const float* W[5]; hf* T[5]; int K[5], N[5]; };
__global__ __launch_bounds__(256) void cvtW(WT5 w){
    const int wi = blockIdx.z;
    const int K = w.K[wi], N = w.N[wi];
    const int n0 = blockIdx.x*32, k0 = blockIdx.y*32;
    if(n0 >= N || k0 >= K) return;
    __shared__ float t[32][33];
    const float* W = w.W[wi]; hf* T = w.T[wi];
    int tx = threadIdx.x, ty = threadIdx.y;
#pragma unroll
    for(int j=0;j<4;j++) t[ty+j*8][tx] = W[(long)(k0+ty+j*8)*N + n0+tx];
    __syncthreads();
#pragma unroll
    for(int j=0;j<4;j++)
        T[(long)(n0+ty+j*8)*K + k0+tx] = __float2half_rn(t[tx][ty+j*8]);
}

// ---- generic fp16 HMMA GEMM: C[m,n] = sum_k A[m,k]*B[n,k], K-chunk = 64 ----
struct GP {
    const hf *A; long ldA, zA_b, zA_h;
    const hf *B; long ldB, zB_b, zB_h;
    int Kc;                          // number of 64-wide K chunks
    float* Cf; hf* Ch; long ldC, zC_b, zC_h;
    const float *bias, *rbias, *rscale; long rs_z;
    float* part;
    float* attnW;                    // fused normalized fp32 write of A-tiles (attnv)
    int mode;                        // 1 = exp epilogue + row partials
    float scale;
};

template<int NTILE>
__global__ __launch_bounds__(256) void gemm_mma(GP p)
{
    constexpr int WC = (NTILE==128)?4:2, WR = 8/WC;
    constexpr int MW = 128/WR, NW = NTILE/WC;   // warp tile
    constexpr int MI = MW/16,  NI = NW/8;
    constexpr int RSTR = 144;                   // 64 halves = 128B + 16B pad
    constexpr int ATILE = 128*RSTR;
    constexpr int BTILE = NTILE*RSTR;
    constexpr int STAGE = ATILE + BTILE;
    constexpr int AREP = 4, BREP = (NTILE==128)?4:2;

    extern __shared__ char smc[];
    float* srow = (float*)smc;                  // 512B: row sums (mode1) / inv cache (attnW)
    const uint32_t smb = s2u(smc);
    const int tid = threadIdx.x, lane = tid&31, w = tid>>5;
    const int wm = w / WC, wn = w % WC;
    const int quad = lane>>2, qi = lane&3;
    const int z = blockIdx.z;
    const long m0 = (long)blockIdx.y*128, n0 = (long)blockIdx.x*NTILE;

    const long zA = (long)(z>>4)*p.zA_b + (long)(z&15)*p.zA_h;
    const long zB = (long)(z>>4)*p.zB_b + (long)(z&15)*p.zB_h;
    const hf *A = p.A + zA, *B = p.B + zB;
    const long zAttn = (long)z*L_*S_;

    if(p.mode==1 && tid < 128) srow[tid] = 0.f;
    if(p.attnW && tid < 128) srow[tid] = p.rscale[(long)z*p.rs_z + m0 + tid];

    auto load_stage = [&](int t, int buf){
        const uint32_t st = smb + 512 + buf*STAGE;
        const long kp = (long)t*64;
#pragma unroll
        for(int rep=0; rep<AREP; rep++){
            int c = tid + rep*256, row = c>>3, cc = c&7;
            cp16(st + row*RSTR + cc*16, A + (m0+row)*p.ldA + kp + cc*8);
        }
#pragma unroll
        for(int rep=0; rep<BREP; rep++){
            int c = tid + rep*256, row = c>>3, cc = c&7;
            cp16(st + ATILE + row*RSTR + cc*16, B + (n0+row)*p.ldB + kp + cc*8);
        }
        CP_COMMIT();
    };

    float acc[MI][NI][4];
#pragma unroll
    for(int i=0;i<MI;i++)
#pragma unroll
        for(int j=0;j<NI;j++)
#pragma unroll
            for(int e=0;e<4;e++) acc[i][j][e] = 0.f;

    // 3-stage pipeline over 64-wide chunks
    load_stage(0, 0);
    if(p.Kc > 1) load_stage(1, 1);

    for(int t = 0; t < p.Kc; t++){
        if(t+2 < p.Kc) { CP_WAIT1(); } else { CP_WAIT0(); }
        __syncthreads();
        if(t+2 < p.Kc) load_stage(t+2, (t+2)%3);

        const int buf = t%3;
        const uint32_t st = smb + 512 + buf*STAGE;
        const uint32_t sB = st + ATILE;

        if(p.attnW){   // fused normalized attn write: each A (P) element passes here once
            const long kp = (long)t*64;
#pragma unroll
            for(int rep=0; rep<AREP; rep++){
                int c = tid + rep*256, row = c>>3, cc = c&7;
                uint4 v = *(uint4*)(smc + 512 + buf*STAGE + row*RSTR + cc*16);
                float iv = srow[row];
                __half2* hp = (__half2*)&v;
                float2 f0=__half22float2(hp[0]), f1=__half22float2(hp[1]);
                float2 f2=__half22float2(hp[2]), f3=__half22float2(hp[3]);
                float* dst = p.attnW + zAttn + (m0+row)*(long)S_ + kp + cc*8;
                *(float4*)dst     = make_float4(f0.x*iv,f0.y*iv,f1.x*iv,f1.y*iv);
                *(float4*)(dst+4) = make_float4(f2.x*iv,f2.y*iv,f3.x*iv,f3.y*iv);
            }
        }

#pragma unroll
        for(int ks=0; ks<4; ks++){
            uint32_t af[MI][4], bfr[NI][2];
            {
                const int j = lane>>3, r = lane&7;
#pragma unroll
                for(int mi=0; mi<MI; mi++){
                    int mrow = wm*MW + mi*16 + (j&1)*8 + r;
                    ldsm4(st + mrow*RSTR + (ks*2 + (j>>1))*16, af[mi]);
                }
            }
            {
                const int j = (lane>>3)&1, r = lane&7;
#pragma unroll
                for(int ni=0; ni<NI; ni++){
                    int nrow = wn*NW + ni*8 + r;
                    ldsm2(sB + nrow*RSTR + (ks*2 + j)*16, bfr[ni]);
                }
            }
#pragma unroll
            for(int mi=0; mi<MI; mi++)
#pragma unroll
                for(int ni=0; ni<NI; ni++)
                    mma16816(acc[mi][ni], af[mi], bfr[ni]);
        }
    }

    // epilogue
    const long zc = (long)(z>>4)*p.zC_b + (long)(z&15)*p.zC_h;
#pragma unroll
    for(int mi=0; mi<MI; mi++){
#pragma unroll
        for(int h=0; h<2; h++){
            const int rl = wm*MW + mi*16 + quad + h*8;
            const long row = m0 + rl;
            const float rs = p.rscale ? p.rscale[(long)z*p.rs_z + row] : 1.f;
            const float rb = p.rbias  ? p.rbias[row] : 0.f;
            float rsum = 0.f;
#pragma unroll
            for(int ni=0; ni<NI; ni++){
                const long col = n0 + wn*NW + ni*8 + qi*2;
                float v0 = acc[mi][ni][2*h]   * rs + rb;
                float v1 = acc[mi][ni][2*h+1] * rs + rb;
                if(p.bias){ v0 += p.bias[col]; v1 += p.bias[col+1]; }
                if(p.mode == 1){
                    v0 = exp2f(v0 * p.scale); v1 = exp2f(v1 * p.scale);
                    rsum += v0 + v1;
                }
                const long o = zc + row*p.ldC + col;
                if(p.Cf) *(float2*)(p.Cf + o) = make_float2(v0, v1);
                if(p.Ch) *(uint32_t*)(p.Ch + o) = pkh(v0, v1);
            }
            if(p.mode == 1) atomicAdd(&srow[rl], rsum);
        }
    }
    if(p.mode == 1){
        __syncthreads();
        if(tid < 128) p.part[((long)z*L_ + m0 + tid)*32 + blockIdx.x] = srow[tid];
    }
}

// ---- reduce partials -> inv row sums ----
__global__ __launch_bounds__(256) void red_inv(const float* __restrict__ part, float* __restrict__ inv){
    const long row = blockIdx.x*8 + (threadIdx.x>>5);
    const int lane = threadIdx.x&31;
    float v = part[row*32 + lane];
#pragma unroll
    for(int o=16;o;o>>=1) v += __shfl_xor_sync(0xffffffffu, v, o);
    if(lane==0) inv[row] = 1.f/v;
}

// ---- host ----
static inline GP base_gp(){ GP p; memset(&p, 0, sizeof(p)); return p; }

extern "C" void kernel_launch(void* const* d_in, const int* in_sizes, int n_in,
                              void* d_out, int out_size)
{
    const float* latent = (const float*)d_in[0];
    const float* x      = (const float*)d_in[1];
    const float* Wq=(const float*)d_in[2], *bq=(const float*)d_in[3];
    const float* Wc=(const float*)d_in[4], *bc=(const float*)d_in[5];
    const float* Wk=(const float*)d_in[6], *bk=(const float*)d_in[7];
    const float* Wv=(const float*)d_in[8], *bv=(const float*)d_in[9];
    const float* Wo=(const float*)d_in[10],*bo=(const float*)d_in[11];
    float* out  = (float*)d_out;
    float* attn = out + (size_t)B_*L_*LD;

    const int SM128 = 512 + 3*(128*144 + 128*144);  // 111104
    const int SM64  = 512 + 3*(128*144 + 64*144);   // 83456
    cudaFuncSetAttribute(gemm_mma<128>, cudaFuncAttributeMaxDynamicSharedMemorySize, SM128);
    cudaFuncSetAttribute(gemm_mma<64>,  cudaFuncAttributeMaxDynamicSharedMemorySize, SM64);

    hf *Lx,*Xx,*WqT,*WcT,*WkT,*WvT,*WoT,*Q,*C,*K,*Vt,*P,*AO;
    float *part,*inv;
    cudaGetSymbolAddress((void**)&Lx,g_Lx);   cudaGetSymbolAddress((void**)&Xx,g_Xx);
    cudaGetSymbolAddress((void**)&WqT,g_WqT); cudaGetSymbolAddress((void**)&WcT,g_WcT);
    cudaGetSymbolAddress((void**)&WkT,g_WkT); cudaGetSymbolAddress((void**)&WvT,g_WvT);
    cudaGetSymbolAddress((void**)&WoT,g_WoT);
    cudaGetSymbolAddress((void**)&Q,g_Q);     cudaGetSymbolAddress((void**)&C,g_C);
    cudaGetSymbolAddress((void**)&K,g_K);     cudaGetSymbolAddress((void**)&Vt,g_Vt);
    cudaGetSymbolAddress((void**)&P,g_P);     cudaGetSymbolAddress((void**)&AO,g_AO);
    cudaGetSymbolAddress((void**)&part,g_part); cudaGetSymbolAddress((void**)&inv,g_inv);

    // second stream + fork/join events (created once; capture-legal)
    static cudaStream_t s1 = 0;
    static cudaEvent_t eS = 0, eA = 0, eW = 0, eC = 0, eK = 0;
    if(!s1){
        cudaStreamCreateWithFlags(&s1, cudaStreamNonBlocking);
        cudaEventCreateWithFlags(&eS, cudaEventDisableTiming);
        cudaEventCreateWithFlags(&eA, cudaEventDisableTiming);
        cudaEventCreateWithFlags(&eW, cudaEventDisableTiming);
        cudaEventCreateWithFlags(&eC, cudaEventDisableTiming);
        cudaEventCreateWithFlags(&eK, cudaEventDisableTiming);
    }

    WT5 wt;
    wt.W[0]=Wq; wt.T[0]=WqT; wt.K[0]=LD; wt.N[0]=LD;
    wt.W[1]=Wc; wt.T[1]=WcT; wt.K[1]=ID; wt.N[1]=R_;
    wt.W[2]=Wk; wt.T[2]=WkT; wt.K[2]=R_; wt.N[2]=LD;
    wt.W[3]=Wv; wt.T[3]=WvT; wt.K[3]=R_; wt.N[3]=LD;
    wt.W[4]=Wo; wt.T[4]=WoT; wt.K[4]=LD; wt.N[4]=LD;
    const long nL = (long)B_*L_*LD/4, nX = (long)B_*S_*ID/4;

    GP p;

    // fork s1 off the main stream
    cudaEventRecord(eS, 0);
    cudaStreamWaitEvent(s1, eS, 0);

    // s1: weight converts -> comp -> K
    cvtW<<<dim3(32, 64, 5), dim3(32,8), 0, s1>>>(wt);
    cudaEventRecord(eW, s1);
    // s0: activation converts
    cvtA<<<4096, 256>>>(latent, x, Lx, Xx, nL, nL + nX);
    cudaEventRecord(eA, 0);

    // s1: compressed = x @ Wc + bc (needs Xx)
    cudaStreamWaitEvent(s1, eA, 0);
    p = base_gp();
    p.A=Xx; p.ldA=ID; p.B=WcT; p.ldB=ID; p.Kc=ID/64;
    p.Ch=C; p.ldC=R_; p.bias=bc;
    gemm_mma<64><<<dim3(R_/64, B_*S_/128, 1), 256, SM64, s1>>>(p);
    cudaEventRecord(eC, s1);
    // s1: K = comp @ Wk + bk
    p = base_gp();
    p.A=C; p.ldA=R_; p.B=WkT; p.ldB=R_; p.Kc=R_/64;
    p.Ch=K; p.ldC=LD; p.bias=bk;
    gemm_mma<128><<<dim3(LD/128, B_*S_/128, 1), 256, SM128, s1>>>(p);
    cudaEventRecord(eK, s1);

    // s0: Q = latent @ Wq + bq (needs WqT)
    cudaStreamWaitEvent(0, eW, 0);
    p = base_gp();
    p.A=Lx; p.ldA=LD; p.B=WqT; p.ldB=LD; p.Kc=LD/64;
    p.Ch=Q; p.ldC=LD; p.bias=bq;
    gemm_mma<64><<<dim3(LD/64, B_*L_/128, 1), 256, SM64>>>(p);

    // s0: Vt[b,d,s] = Wv^T[d,:] . comp_b[s,:] + bv[d] (needs C)
    cudaStreamWaitEvent(0, eC, 0);
    p = base_gp();
    p.A=WvT; p.ldA=R_;
    p.B=C; p.ldB=R_; p.zB_h=(long)S_*R_;
    p.Kc=R_/64; p.Ch=Vt; p.ldC=S_; p.zC_h=(long)LD*S_; p.rbias=bv;
    gemm_mma<128><<<dim3(S_/128, LD/128, B_), 256, SM128>>>(p);

    // s0: scores (needs K) — Kc=1: single chunk of 64
    cudaStreamWaitEvent(0, eK, 0);
    p = base_gp();
    p.A=Q; p.ldA=LD; p.zA_b=(long)L_*LD; p.zA_h=64;
    p.B=K; p.ldB=LD; p.zB_b=(long)S_*LD; p.zB_h=64;
    p.Kc=1; p.Ch=P; p.ldC=S_; p.zC_b=(long)H_*L_*S_; p.zC_h=(long)L_*S_;
    p.mode=1; p.scale=0.125f*1.44269504088896340736f; p.part=part;
    gemm_mma<128><<<dim3(S_/128, L_/128, B_*H_), 256, SM128>>>(p);
    // s0: reduce partials -> 1/rowsum
    red_inv<<<(B_*H_*L_)/8, 256>>>(part, inv);
    // s0: attn_out = (P @ Vt^T) * inv(row); fused normalized fp32 attn write
    p = base_gp();
    p.A=P; p.ldA=S_; p.zA_b=(long)H_*L_*S_; p.zA_h=(long)L_*S_;
    p.B=Vt; p.ldB=S_; p.zB_b=(long)LD*S_; p.zB_h=(long)64*S_;
    p.Kc=S_/64; p.Ch=AO; p.ldC=LD; p.zC_b=(long)L_*LD; p.zC_h=64;
    p.rscale=inv; p.rs_z=L_; p.attnW=attn;
    gemm_mma<64><<<dim3(1, L_/128, B_*H_), 256, SM64>>>(p);
    // s0: output = AO @ Wo + bo
    p = base_gp();
    p.A=AO; p.ldA=LD; p.B=WoT; p.ldB=LD; p.Kc=LD/64;
    p.Cf=out; p.ldC=LD; p.bias=bo;
    gemm_mma<64><<<dim3(LD/64, B_*L_/128, 1), 256, SM64>>>(p);
}

// round 14
// speedup vs baseline: 3.6613x; 1.0190x over previous
#include <cuda_runtime.h>
#include <cuda_fp16.h>
#include <cstdint>
#include <string.h>
#include <math.h>

#define B_  2
#define L_  1024
#define S_  4096
#define H_  16
#define LD  1024
#define ID  2048
#define R_  256

typedef __half hf;

// ---- scratch (device globals, allocation-free) ----
__device__ hf g_Lx[B_*L_*LD];
__device__ hf g_Xx[B_*S_*ID];
__device__ hf g_WqT[LD*LD], g_WcT[R_*ID], g_WkT[LD*R_], g_WvT[LD*R_], g_WoT[LD*LD];
__device__ hf g_Q[B_*L_*LD];
__device__ hf g_C[B_*S_*R_];
__device__ hf g_K[B_*S_*LD];
__device__ hf g_Vt[B_*LD*S_];
__device__ hf g_P[(size_t)B_*H_*L_*S_];
__device__ hf g_AO[B_*L_*LD];
__device__ float g_part[(size_t)B_*H_*L_*32];
__device__ float g_inv[B_*H_*L_];

// ---- helpers ----
__device__ __forceinline__ uint32_t s2u(const void* p){ uint32_t a; asm("{ .reg .u64 t; cvta.to.shared.u64 t, %1; cvt.u32.u64 %0, t; }":"=r"(a):"l"(p)); return a; }
__device__ __forceinline__ void cp16(uint32_t d, const void* g){ asm volatile("cp.async.cg.shared.global [%0],[%1],16;"::"r"(d),"l"(g)); }
#define CP_COMMIT() asm volatile("cp.async.commit_group;":::"memory")
#define CP_WAIT0()  asm volatile("cp.async.wait_group 0;":::"memory")
__device__ __forceinline__ void ldsm4(uint32_t a, uint32_t* r){
    asm volatile("ldmatrix.sync.aligned.m8n8.x4.shared.b16 {%0,%1,%2,%3},[%4];"
        :"=r"(r[0]),"=r"(r[1]),"=r"(r[2]),"=r"(r[3]):"r"(a));
}
__device__ __forceinline__ void mma16816(float* c, const uint32_t* a, const uint32_t* b){
    asm volatile("mma.sync.aligned.m16n8k16.row.col.f32.f16.f16.f32 "
        "{%0,%1,%2,%3},{%4,%5,%6,%7},{%8,%9},{%0,%1,%2,%3};"
        :"+f"(c[0]),"+f"(c[1]),"+f"(c[2]),"+f"(c[3])
        :"r"(a[0]),"r"(a[1]),"r"(a[2]),"r"(a[3]),"r"(b[0]),"r"(b[1]));
}
__device__ __forceinline__ uint32_t pkh(float a, float b){ __half2 t=__floats2half2_rn(a,b); return *(uint32_t*)&t; }

// ---- fused activation convert: latent + x in one launch ----
__global__ __launch_bounds__(256) void cvtA(const float* __restrict__ lat, const float* __restrict__ x,
                                            hf* __restrict__ Lx, hf* __restrict__ Xx, long nL, long nT){
    for(long i = blockIdx.x*256L + threadIdx.x; i < nT; i += (long)gridDim.x*256){
        const float4 v = (i < nL) ? ((const float4*)lat)[i] : ((const float4*)x)[i - nL];
        uint2 o = make_uint2(pkh(v.x,v.y), pkh(v.z,v.w));
        if(i < nL) ((uint2*)Lx)[i] = o; else ((uint2*)Xx)[i - nL] = o;
    }
}
// ---- fused weight transpose-convert: 5 weights, z-selected ----
struct WT5 { const float* W[5]; hf* T[5]; int K[5], N[5]; };
__global__ __launch_bounds__(256) void cvtW(WT5 w){
    const int wi = blockIdx.z;
    const int K = w.K[wi], N = w.N[wi];
    const int n0 = blockIdx.x*32, k0 = blockIdx.y*32;
    if(n0 >= N || k0 >= K) return;
    __shared__ float t[32][33];
    const float* W = w.W[wi]; hf* T = w.T[wi];
    int tx = threadIdx.x, ty = threadIdx.y;
#pragma unroll
    for(int j=0;j<4;j++) t[ty+j*8][tx] = W[(long)(k0+ty+j*8)*N + n0+tx];
    __syncthreads();
#pragma unroll
    for(int j=0;j<4;j++)
        T[(long)(n0+ty+j*8)*K + k0+tx] = __float2half_rn(t[tx][ty+j*8]);
}

// ---- generic fp16 HMMA GEMM: C[m,n] = sum_k A[m,k]*B[n,k], K-chunk = 64 ----
struct GP {
    const hf *A; long ldA, zA_b, zA_h;
    const hf *B; long ldB, zB_b, zB_h;
    int Kc;                          // number of 64-wide K chunks
    float* Cf; hf* Ch; long ldC, zC_b, zC_h;
    const float *bias, *rbias, *rscale; long rs_z;
    float* part;
    float* attnW;                    // fused normalized fp32 write of A-tiles (attnv)
    int mode;                        // 1 = exp epilogue + row partials
    float scale;
};

template<int NTILE>
__global__ __launch_bounds__(256) void gemm_mma(GP p)
{
    constexpr int WC = (NTILE==128)?4:2, WR = 8/WC;
    constexpr int MW = 128/WR, NW = NTILE/WC;   // warp tile
    constexpr int MI = MW/16,  NI = NW/8;
    constexpr int RSTR = 144;                   // 64 halves = 128B + 16B pad
    constexpr int ATILE = 128*RSTR;
    constexpr int BTILE = NTILE*RSTR;
    constexpr int STAGE = ATILE + BTILE;
    constexpr int AREP = 4, BREP = (NTILE==128)?4:2;

    extern __shared__ char smc[];
    float* srow = (float*)smc;                  // 512B: row sums (mode1) / inv cache (attnW)
    const uint32_t smb = s2u(smc);
    const int tid = threadIdx.x, lane = tid&31, w = tid>>5;
    const int wm = w / WC, wn = w % WC;
    const int quad = lane>>2, qi = lane&3;
    const int z = blockIdx.z;
    const long m0 = (long)blockIdx.y*128, n0 = (long)blockIdx.x*NTILE;

    const long zA = (long)(z>>4)*p.zA_b + (long)(z&15)*p.zA_h;
    const long zB = (long)(z>>4)*p.zB_b + (long)(z&15)*p.zB_h;
    const hf *A = p.A + zA, *B = p.B + zB;
    const long zAttn = (long)z*L_*S_;

    if(p.mode==1 && tid < 128) srow[tid] = 0.f;
    if(p.attnW && tid < 128) srow[tid] = p.rscale[(long)z*p.rs_z + m0 + tid];

    auto load_stage = [&](int t, int buf){
        const uint32_t st = smb + 512 + buf*STAGE;
        const long kp = (long)t*64;
#pragma unroll
        for(int rep=0; rep<AREP; rep++){
            int c = tid + rep*256, row = c>>3, cc = c&7;
            cp16(st + row*RSTR + cc*16, A + (m0+row)*p.ldA + kp + cc*8);
        }
#pragma unroll
        for(int rep=0; rep<BREP; rep++){
            int c = tid + rep*256, row = c>>3, cc = c&7;
            cp16(st + ATILE + row*RSTR + cc*16, B + (n0+row)*p.ldB + kp + cc*8);
        }
        CP_COMMIT();
    };

    float acc[MI][NI][4];
#pragma unroll
    for(int i=0;i<MI;i++)
#pragma unroll
        for(int j=0;j<NI;j++)
#pragma unroll
            for(int e=0;e<4;e++) acc[i][j][e] = 0.f;

    // 2-stage pipeline over 64-wide chunks
    load_stage(0, 0);

    for(int t = 0; t < p.Kc; t++){
        CP_WAIT0();
        __syncthreads();
        if(t+1 < p.Kc) load_stage(t+1, (t+1)&1);

        const int buf = t&1;
        const uint32_t st = smb + 512 + buf*STAGE;
        const uint32_t sB = st + ATILE;

        if(p.attnW){   // fused normalized attn write: each A (P) element passes here once
            const long kp = (long)t*64;
#pragma unroll
            for(int rep=0; rep<AREP; rep++){
                int c = tid + rep*256, row = c>>3, cc = c&7;
                uint4 v = *(uint4*)(smc + 512 + buf*STAGE + row*RSTR + cc*16);
                float iv = srow[row];
                __half2* hp = (__half2*)&v;
                float2 f0=__half22float2(hp[0]), f1=__half22float2(hp[1]);
                float2 f2=__half22float2(hp[2]), f3=__half22float2(hp[3]);
                float* dst = p.attnW + zAttn + (m0+row)*(long)S_ + kp + cc*8;
                *(float4*)dst     = make_float4(f0.x*iv,f0.y*iv,f1.x*iv,f1.y*iv);
                *(float4*)(dst+4) = make_float4(f2.x*iv,f2.y*iv,f3.x*iv,f3.y*iv);
            }
        }

#pragma unroll
        for(int ks=0; ks<4; ks++){
            uint32_t af[MI][4], bfr[NI][2];
            {
                const int j = lane>>3, r = lane&7;
#pragma unroll
                for(int mi=0; mi<MI; mi++){
                    int mrow = wm*MW + mi*16 + (j&1)*8 + r;
                    ldsm4(st + mrow*RSTR + (ks*2 + (j>>1))*16, af[mi]);
                }
            }
            {
                // B via ldmatrix.x4: two adjacent n8 tiles per instruction
                const int g = lane>>3, r = lane&7;
#pragma unroll
                for(int ni=0; ni<NI; ni+=2){
                    int nrow = wn*NW + ni*8 + (g>>1)*8 + r;
                    uint32_t a = sB + nrow*RSTR + (ks*2 + (g&1))*16;
                    uint32_t rr[4]; ldsm4(a, rr);
                    bfr[ni][0]=rr[0];   bfr[ni][1]=rr[1];
                    bfr[ni+1][0]=rr[2]; bfr[ni+1][1]=rr[3];
                }
            }
#pragma unroll
            for(int mi=0; mi<MI; mi++)
#pragma unroll
                for(int ni=0; ni<NI; ni++)
                    mma16816(acc[mi][ni], af[mi], bfr[ni]);
        }
    }

    // epilogue
    const long zc = (long)(z>>4)*p.zC_b + (long)(z&15)*p.zC_h;
#pragma unroll
    for(int mi=0; mi<MI; mi++){
#pragma unroll
        for(int h=0; h<2; h++){
            const int rl = wm*MW + mi*16 + quad + h*8;
            const long row = m0 + rl;
            const float rs = p.rscale ? p.rscale[(long)z*p.rs_z + row] : 1.f;
            const float rb = p.rbias  ? p.rbias[row] : 0.f;
            float rsum = 0.f;
#pragma unroll
            for(int ni=0; ni<NI; ni++){
                const long col = n0 + wn*NW + ni*8 + qi*2;
                float v0 = acc[mi][ni][2*h]   * rs + rb;
                float v1 = acc[mi][ni][2*h+1] * rs + rb;
                if(p.bias){ v0 += p.bias[col]; v1 += p.bias[col+1]; }
                if(p.mode == 1){
                    v0 = exp2f(v0 * p.scale); v1 = exp2f(v1 * p.scale);
                    rsum += v0 + v1;
                }
                const long o = zc + row*p.ldC + col;
                if(p.Cf) *(float2*)(p.Cf + o) = make_float2(v0, v1);
                if(p.Ch) *(uint32_t*)(p.Ch + o) = pkh(v0, v1);
            }
            if(p.mode == 1) atomicAdd(&srow[rl], rsum);
        }
    }
    if(p.mode == 1){
        __syncthreads();
        if(tid < 128) p.part[((long)z*L_ + m0 + tid)*32 + blockIdx.x] = srow[tid];
    }
}

// ---- reduce partials -> inv row sums ----
__global__ __launch_bounds__(256) void red_inv(const float* __restrict__ part, float* __restrict__ inv){
    const long row = blockIdx.x*8 + (threadIdx.x>>5);
    const int lane = threadIdx.x&31;
    float v = part[row*32 + lane];
#pragma unroll
    for(int o=16;o;o>>=1) v += __shfl_xor_sync(0xffffffffu, v, o);
    if(lane==0) inv[row] = 1.f/v;
}

// ---- host ----
static inline GP base_gp(){ GP p; memset(&p, 0, sizeof(p)); return p; }

extern "C" void kernel_launch(void* const* d_in, const int* in_sizes, int n_in,
                              void* d_out, int out_size)
{
    const float* latent = (const float*)d_in[0];
    const float* x      = (const float*)d_in[1];
    const float* Wq=(const float*)d_in[2], *bq=(const float*)d_in[3];
    const float* Wc=(const float*)d_in[4], *bc=(const float*)d_in[5];
    const float* Wk=(const float*)d_in[6], *bk=(const float*)d_in[7];
    const float* Wv=(const float*)d_in[8], *bv=(const float*)d_in[9];
    const float* Wo=(const float*)d_in[10],*bo=(const float*)d_in[11];
    float* out  = (float*)d_out;
    float* attn = out + (size_t)B_*L_*LD;

    const int SM128 = 512 + 2*(128*144 + 128*144);  // 74240
    const int SM64  = 512 + 2*(128*144 + 64*144);   // 55808
    cudaFuncSetAttribute(gemm_mma<128>, cudaFuncAttributeMaxDynamicSharedMemorySize, SM128);
    cudaFuncSetAttribute(gemm_mma<64>,  cudaFuncAttributeMaxDynamicSharedMemorySize, SM64);

    hf *Lx,*Xx,*WqT,*WcT,*WkT,*WvT,*WoT,*Q,*C,*K,*Vt,*P,*AO;
    float *part,*inv;
    cudaGetSymbolAddress((void**)&Lx,g_Lx);   cudaGetSymbolAddress((void**)&Xx,g_Xx);
    cudaGetSymbolAddress((void**)&WqT,g_WqT); cudaGetSymbolAddress((void**)&WcT,g_WcT);
    cudaGetSymbolAddress((void**)&WkT,g_WkT); cudaGetSymbolAddress((void**)&WvT,g_WvT);
    cudaGetSymbolAddress((void**)&WoT,g_WoT);
    cudaGetSymbolAddress((void**)&Q,g_Q);     cudaGetSymbolAddress((void**)&C,g_C);
    cudaGetSymbolAddress((void**)&K,g_K);     cudaGetSymbolAddress((void**)&Vt,g_Vt);
    cudaGetSymbolAddress((void**)&P,g_P);     cudaGetSymbolAddress((void**)&AO,g_AO);
    cudaGetSymbolAddress((void**)&part,g_part); cudaGetSymbolAddress((void**)&inv,g_inv);

    // second stream + fork/join events (created once; capture-legal)
    static cudaStream_t s1 = 0;
    static cudaEvent_t eS = 0, eA = 0, eW = 0, eC = 0, eK = 0;
    if(!s1){
        cudaStreamCreateWithFlags(&s1, cudaStreamNonBlocking);
        cudaEventCreateWithFlags(&eS, cudaEventDisableTiming);
        cudaEventCreateWithFlags(&eA, cudaEventDisableTiming);
        cudaEventCreateWithFlags(&eW, cudaEventDisableTiming);
        cudaEventCreateWithFlags(&eC, cudaEventDisableTiming);
        cudaEventCreateWithFlags(&eK, cudaEventDisableTiming);
    }

    WT5 wt;
    wt.W[0]=Wq; wt.T[0]=WqT; wt.K[0]=LD; wt.N[0]=LD;
    wt.W[1]=Wc; wt.T[1]=WcT; wt.K[1]=ID; wt.N[1]=R_;
    wt.W[2]=Wk; wt.T[2]=WkT; wt.K[2]=R_; wt.N[2]=LD;
    wt.W[3]=Wv; wt.T[3]=WvT; wt.K[3]=R_; wt.N[3]=LD;
    wt.W[4]=Wo; wt.T[4]=WoT; wt.K[4]=LD; wt.N[4]=LD;
    const long nL = (long)B_*L_*LD/4, nX = (long)B_*S_*ID/4;

    GP p;

    // fork s1 off the main stream
    cudaEventRecord(eS, 0);
    cudaStreamWaitEvent(s1, eS, 0);

    // s1: weight converts
    cvtW<<<dim3(32, 64, 5), dim3(32,8), 0, s1>>>(wt);
    cudaEventRecord(eW, s1);
    // s0: activation converts
    cvtA<<<4096, 256>>>(latent, x, Lx, Xx, nL, nL + nX);
    cudaEventRecord(eA, 0);

    // s1: compressed = x @ Wc + bc (needs Xx)
    cudaStreamWaitEvent(s1, eA, 0);
    p = base_gp();
    p.A=Xx; p.ldA=ID; p.B=WcT; p.ldB=ID; p.Kc=ID/64;
    p.Ch=C; p.ldC=R_; p.bias=bc;
    gemm_mma<64><<<dim3(R_/64, B_*S_/128, 1), 256, SM64, s1>>>(p);
    cudaEventRecord(eC, s1);
    // s1: K = comp @ Wk + bk
    p = base_gp();
    p.A=C; p.ldA=R_; p.B=WkT; p.ldB=R_; p.Kc=R_/64;
    p.Ch=K; p.ldC=LD; p.bias=bk;
    gemm_mma<128><<<dim3(LD/128, B_*S_/128, 1), 256, SM128, s1>>>(p);
    cudaEventRecord(eK, s1);

    // s0: Q = latent @ Wq + bq (needs WqT)
    cudaStreamWaitEvent(0, eW, 0);
    p = base_gp();
    p.A=Lx; p.ldA=LD; p.B=WqT; p.ldB=LD; p.Kc=LD/64;
    p.Ch=Q; p.ldC=LD; p.bias=bq;
    gemm_mma<64><<<dim3(LD/64, B_*L_/128, 1), 256, SM64>>>(p);

    // s0: Vt[b,d,s] = Wv^T[d,:] . comp_b[s,:] + bv[d] (needs C)
    cudaStreamWaitEvent(0, eC, 0);
    p = base_gp();
    p.A=WvT; p.ldA=R_;
    p.B=C; p.ldB=R_; p.zB_h=(long)S_*R_;
    p.Kc=R_/64; p.Ch=Vt; p.ldC=S_; p.zC_h=(long)LD*S_; p.rbias=bv;
    gemm_mma<128><<<dim3(S_/128, LD/128, B_), 256, SM128>>>(p);

    // s0: scores (needs K) — Kc=1: single chunk of 64
    cudaStreamWaitEvent(0, eK, 0);
    p = base_gp();
    p.A=Q; p.ldA=LD; p.zA_b=(long)L_*LD; p.zA_h=64;
    p.B=K; p.ldB=LD; p.zB_b=(long)S_*LD; p.zB_h=64;
    p.Kc=1; p.Ch=P; p.ldC=S_; p.zC_b=(long)H_*L_*S_; p.zC_h=(long)L_*S_;
    p.mode=1; p.scale=0.125f*1.44269504088896340736f; p.part=part;
    gemm_mma<128><<<dim3(S_/128, L_/128, B_*H_), 256, SM128>>>(p);
    // s0: reduce partials -> 1/rowsum
    red_inv<<<(B_*H_*L_)/8, 256>>>(part, inv);
    // s0: attn_out = (P @ Vt^T) * inv(row); fused normalized fp32 attn write
    p = base_gp();
    p.A=P; p.ldA=S_; p.zA_b=(long)H_*L_*S_; p.zA_h=(long)L_*S_;
    p.B=Vt; p.ldB=S_; p.zB_b=(long)LD*S_; p.zB_h=(long)64*S_;
    p.Kc=S_/64; p.Ch=AO; p.ldC=LD; p.zC_b=(long)L_*LD; p.zC_h=64;
    p.rscale=inv; p.rs_z=L_; p.attnW=attn;
    gemm_mma<64><<<dim3(1, L_/128, B_*H_), 256, SM64>>>(p);
    // s0: output = AO @ Wo + bo
    p = base_gp();
    p.A=AO; p.ldA=LD; p.B=WoT; p.ldB=LD; p.Kc=LD/64;
    p.Cf=out; p.ldC=LD; p.bias=bo;
    gemm_mma<64><<<dim3(LD/64, B_*L_/128, 1), 256, SM64>>>(p);
}